// round 14
// baseline (speedup 1.0000x reference)
#include <cuda_runtime.h>
#include <math.h>
#include <stdint.h>

#define D      512
#define T      256
#define TOPK   8
#define NPAIR  2048
#define NEXP   16
#define MAXH   2560
#define NSCORE 4096

// ---------------- scratch ----------------------------------------------------
__device__ float g_h1[T * D];
__device__ float g_h2[T * 256];
__device__ float g_scores[2 * T * NSCORE];   // 2 split-K partials (fc3)
__device__ float g_preu[2 * NPAIR * D];      // 2 split-K partials
__device__ float g_xin[NPAIR * D];
__device__ float g_hmid[NPAIR * MAXH];
__device__ float g_y4[4 * NPAIR * D];        // 4 split-K partials (mlp2)
__device__ float g_y[NPAIR * D];
__device__ float g_z[2 * NPAIR * D];         // 2 split-K partials (post)
__device__ float g_w[NPAIR];
__device__ int   g_prei[NPAIR];
__device__ int   g_mlpi[NPAIR];
__device__ int   g_posti[NPAIR];
__device__ int   g_cnt[48];
__device__ int   g_rows[48 * NPAIR];

// ---------------- helpers ----------------------------------------------------
__device__ __forceinline__ float actf(int a, float v) {
    switch (a) {
        case 0: return 0.5f * v * (1.0f + erff(v * 0.7071067811865476f));
        case 1: return fmaxf(v, 0.0f);
        case 2: return tanhf(v);
        default: return v / (1.0f + expf(-v));
    }
}

__device__ __forceinline__ unsigned f2tf32(float f) {
    unsigned r;
    asm("cvt.rna.tf32.f32 %0, %1;" : "=r"(r) : "f"(f));
    return r;
}

__device__ __forceinline__ uint32_t sptr(const void* p) {
    return (uint32_t)__cvta_generic_to_shared(p);
}

__device__ __forceinline__ void cpa16(uint32_t d, const float* s, bool pred) {
    int sz = pred ? 16 : 0;
    asm volatile("cp.async.cg.shared.global [%0], [%1], 16, %2;"
                 :: "r"(d), "l"(s), "r"(sz));
}

__device__ __forceinline__ float wsum(float v) {
#pragma unroll
    for (int o = 16; o; o >>= 1) v += __shfl_xor_sync(0xffffffffu, v, o);
    return v;
}
__device__ __forceinline__ float wmax(float v) {
#pragma unroll
    for (int o = 16; o; o >>= 1) v = fmaxf(v, __shfl_xor_sync(0xffffffffu, v, o));
    return v;
}

#define MMA_TF32(c, a0, a1, a2, a3, b0, b1)                                      \
    asm volatile("mma.sync.aligned.m16n8k8.row.col.f32.tf32.tf32.f32 "           \
                 "{%0,%1,%2,%3}, {%4,%5,%6,%7}, {%8,%9}, {%0,%1,%2,%3};"         \
                 : "+f"((c)[0]), "+f"((c)[1]), "+f"((c)[2]), "+f"((c)[3])        \
                 : "r"(a0), "r"(a1), "r"(a2), "r"(a3), "r"(b0), "r"(b1))

struct GArgs {
    const float* A; int lda;
    const float* B; long bStride; int ldb;
    const float* bias; int biasStride;
    float* C; int ldc;
    int M, N, K;
    const int* rows; const int* cnt;
    int gshift;
    int varN, varK;
    int act;            // 0 none, 1..4 fixed (act-1), 5 per-expert e&3
    long cStride;       // split-K partial-buffer stride (elements); 0 = no split
    int* zcnt;          // if non-null: block (0,0,0) zeroes 48 counters
};

// ---------------- tf32 grouped GEMM (experts), split-K capable ---------------
// BM=32, BN=64; 64 threads = 2 warps; warp tile 32x32; S-stage cp.async.
template<int SPLIT, int S>
__global__ __launch_bounds__(64) void tgemm_k(GArgs g) {
    constexpr int BM  = 32;
    constexpr int BN  = 64;
    constexpr int MI  = 2;
    constexpr int NI  = 4;
    constexpr int BNP = BN + 8;

    const int e  = blockIdx.z;
    const int Me = g.cnt[e];
    if (Me == 0) return;
    const int he = 512 * (2 + (e >> 2));
    const int Ne = g.varN ? he : g.N;
    const int Ke = g.varK ? he : g.K;

    const int ntiles = gridDim.x / SPLIT;
    const int slice  = blockIdx.x / ntiles;
    const int n0     = (blockIdx.x % ntiles) * BN;
    if (n0 >= Ne) return;

    const int Ksl   = Ke / SPLIT;
    const int kbase = slice * Ksl;
    const int KT    = Ksl >> 4;

    float* Cp = g.C + (long)slice * g.cStride;

    const float* Bp = g.B + (long)e * g.bStride;
    const int*   rl = g.rows + e * NPAIR;

    __shared__ float As[S][BM][20];
    __shared__ float Bs[S][16][BNP];

    const int tid = threadIdx.x, lane = tid & 31;
    const int wn = tid >> 5;
    const int grp = lane >> 2, t4 = lane & 3;
    const int a_row = tid >> 1;
    const int aq    = (tid & 1) * 2;

    const int aAct = (g.act == 5) ? (e & 3) : (g.act - 1);

    for (int m0 = blockIdx.y * BM; m0 < Me; m0 += gridDim.y * BM) {
        const bool mv = (m0 + a_row) < Me;
        long arow = 0;
        if (mv) arow = (long)(rl[m0 + a_row] >> g.gshift);
        const float* Ap = g.A + arow * (long)g.lda + kbase;

        int crow[MI * 2];
#pragma unroll
        for (int mi = 0; mi < MI; mi++)
#pragma unroll
            for (int h = 0; h < 2; h++) {
                int m = m0 + mi * 16 + grp + h * 8;
                crow[mi * 2 + h] = (m < Me) ? rl[m] : -1;
            }

        float acc[MI][NI][4];
#pragma unroll
        for (int mi = 0; mi < MI; mi++)
#pragma unroll
            for (int ni = 0; ni < NI; ni++)
#pragma unroll
                for (int c = 0; c < 4; c++) acc[mi][ni][c] = 0.0f;

        auto loadStage = [&](int s, int kt) {
            int k0 = kt << 4;
#pragma unroll
            for (int i = 0; i < 2; i++)
                cpa16(sptr(&As[s][a_row][(aq + i) * 4]), Ap + k0 + (aq + i) * 4, mv);
#pragma unroll
            for (int i = 0; i < 4; i++) {
                int idx = tid + i * 64;
                int r = idx >> 4, col = (idx & 15) * 4;
                cpa16(sptr(&Bs[s][r][col]),
                      Bp + (long)(kbase + k0 + r) * g.ldb + n0 + col, true);
            }
            asm volatile("cp.async.commit_group;");
        };

#pragma unroll
        for (int s = 0; s < S - 1; s++) {
            if (s < KT) loadStage(s, s);
            else        asm volatile("cp.async.commit_group;");
        }

        for (int kt = 0; kt < KT; kt++) {
            asm volatile("cp.async.wait_group %0;" :: "n"(S - 2));
            __syncthreads();
            const int buf = kt % S;

            if (kt + S - 1 < KT) loadStage((kt + S - 1) % S, kt + S - 1);
            else                 asm volatile("cp.async.commit_group;");

#pragma unroll
            for (int ks = 0; ks < 2; ks++) {
                const int kk = ks * 8;
                unsigned a[MI][4], b[NI][2];
#pragma unroll
                for (int mi = 0; mi < MI; mi++) {
                    int mr = mi * 16 + grp;
                    a[mi][0] = f2tf32(As[buf][mr][kk + t4]);
                    a[mi][1] = f2tf32(As[buf][mr + 8][kk + t4]);
                    a[mi][2] = f2tf32(As[buf][mr][kk + t4 + 4]);
                    a[mi][3] = f2tf32(As[buf][mr + 8][kk + t4 + 4]);
                }
#pragma unroll
                for (int ni = 0; ni < NI; ni++) {
                    int nc = wn * 32 + ni * 8 + grp;
                    b[ni][0] = f2tf32(Bs[buf][kk + t4][nc]);
                    b[ni][1] = f2tf32(Bs[buf][kk + t4 + 4][nc]);
                }
#pragma unroll
                for (int mi = 0; mi < MI; mi++)
#pragma unroll
                    for (int ni = 0; ni < NI; ni++)
                        MMA_TF32(acc[mi][ni], a[mi][0], a[mi][1], a[mi][2], a[mi][3],
                                 b[ni][0], b[ni][1]);
            }
        }

#pragma unroll
        for (int ni = 0; ni < NI; ni++) {
            int c = n0 + wn * 32 + ni * 8 + t4 * 2;
            float b0 = 0.0f, b1 = 0.0f;
            if (SPLIT == 1) {
                const float* bias = g.bias + (long)e * g.biasStride;
                b0 = bias[c]; b1 = bias[c + 1];
            }
#pragma unroll
            for (int mi = 0; mi < MI; mi++)
#pragma unroll
                for (int h = 0; h < 2; h++) {
                    int cr = crow[mi * 2 + h];
                    if (cr >= 0) {
                        float v0 = acc[mi][ni][h * 2 + 0] + b0;
                        float v1 = acc[mi][ni][h * 2 + 1] + b1;
                        if (SPLIT == 1 && aAct >= 0) { v0 = actf(aAct, v0); v1 = actf(aAct, v1); }
                        *(float2*)(Cp + (long)cr * g.ldc + c) = make_float2(v0, v1);
                    }
                }
        }
        asm volatile("cp.async.wait_group 0;");
        __syncthreads();
    }
}

// ---------------- router GEMM: split-tf32 (hi/lo), optional split-K ----------
__global__ __launch_bounds__(256) void rgemm_k(GArgs g) {
    const int n0 = blockIdx.x * 64;
    const int m0 = blockIdx.y * 128;
    if (n0 >= g.N) return;
    const int slice = blockIdx.z;

    if (g.zcnt && blockIdx.x == 0 && blockIdx.y == 0 && slice == 0 && threadIdx.x < 48)
        g.zcnt[threadIdx.x] = 0;

    __shared__ unsigned AsH[128][20], AsL[128][20];
    __shared__ unsigned BsH[16][72], BsL[16][72];

    const int tid = threadIdx.x, warp = tid >> 5, lane = tid & 31;
    const int grp = lane >> 2, t4 = lane & 3;
    const int wm = warp >> 1, wn = warp & 1;
    const int a_row = tid >> 1;
    const int aq = (tid & 1) * 2;
    const int bk = tid >> 4, cb = (tid & 15) * 4;

    const bool mv = (m0 + a_row) < g.M;
    const float* Ap = g.A + (long)(m0 + a_row) * g.lda + (long)slice * g.K;
    const float* Bp = g.B + (long)slice * g.K * g.ldb;
    float* Cp = g.C + (long)slice * g.cStride;
    const bool full = (g.cStride == 0);

    float acc[2][4][4];
#pragma unroll
    for (int mi = 0; mi < 2; mi++)
#pragma unroll
        for (int ni = 0; ni < 4; ni++)
#pragma unroll
            for (int c = 0; c < 4; c++) acc[mi][ni][c] = 0.0f;

    float4 av[2], bv;
    auto ldreg = [&](int k0) {
#pragma unroll
        for (int i = 0; i < 2; i++)
            av[i] = mv ? *(const float4*)(Ap + k0 + (aq + i) * 4)
                       : make_float4(0.f, 0.f, 0.f, 0.f);
        bv = *(const float4*)(Bp + (long)(k0 + bk) * g.ldb + n0 + cb);
    };

    const int KT = g.K >> 4;
    ldreg(0);
    for (int kt = 0; kt < KT; kt++) {
        __syncthreads();
#pragma unroll
        for (int i = 0; i < 2; i++) {
            float vv[4] = {av[i].x, av[i].y, av[i].z, av[i].w};
            uint4 uh, ul;
            unsigned* ph = &uh.x; unsigned* pl = &ul.x;
#pragma unroll
            for (int c = 0; c < 4; c++) {
                unsigned hb = f2tf32(vv[c]);
                ph[c] = hb;
                pl[c] = f2tf32(vv[c] - __uint_as_float(hb));
            }
            *(uint4*)&AsH[a_row][(aq + i) * 4] = uh;
            *(uint4*)&AsL[a_row][(aq + i) * 4] = ul;
        }
        {
            float vv[4] = {bv.x, bv.y, bv.z, bv.w};
            uint4 uh, ul;
            unsigned* ph = &uh.x; unsigned* pl = &ul.x;
#pragma unroll
            for (int c = 0; c < 4; c++) {
                unsigned hb = f2tf32(vv[c]);
                ph[c] = hb;
                pl[c] = f2tf32(vv[c] - __uint_as_float(hb));
            }
            *(uint4*)&BsH[bk][cb] = uh;
            *(uint4*)&BsL[bk][cb] = ul;
        }
        __syncthreads();

        if (kt + 1 < KT) ldreg((kt + 1) << 4);

#pragma unroll
        for (int ks = 0; ks < 2; ks++) {
            const int kk = ks * 8;
            unsigned ah[2][4], al[2][4], bh[4][2], bl[4][2];
#pragma unroll
            for (int mi = 0; mi < 2; mi++) {
                int mr = wm * 32 + mi * 16 + grp;
                ah[mi][0] = AsH[mr][kk + t4];     al[mi][0] = AsL[mr][kk + t4];
                ah[mi][1] = AsH[mr + 8][kk + t4]; al[mi][1] = AsL[mr + 8][kk + t4];
                ah[mi][2] = AsH[mr][kk + t4 + 4]; al[mi][2] = AsL[mr][kk + t4 + 4];
                ah[mi][3] = AsH[mr + 8][kk + t4 + 4]; al[mi][3] = AsL[mr + 8][kk + t4 + 4];
            }
#pragma unroll
            for (int ni = 0; ni < 4; ni++) {
                int nc = wn * 32 + ni * 8 + grp;
                bh[ni][0] = BsH[kk + t4][nc];     bl[ni][0] = BsL[kk + t4][nc];
                bh[ni][1] = BsH[kk + t4 + 4][nc]; bl[ni][1] = BsL[kk + t4 + 4][nc];
            }
#pragma unroll
            for (int mi = 0; mi < 2; mi++)
#pragma unroll
                for (int ni = 0; ni < 4; ni++) {
                    MMA_TF32(acc[mi][ni], ah[mi][0], ah[mi][1], ah[mi][2], ah[mi][3],
                             bh[ni][0], bh[ni][1]);
                    MMA_TF32(acc[mi][ni], ah[mi][0], ah[mi][1], ah[mi][2], ah[mi][3],
                             bl[ni][0], bl[ni][1]);
                    MMA_TF32(acc[mi][ni], al[mi][0], al[mi][1], al[mi][2], al[mi][3],
                             bh[ni][0], bh[ni][1]);
                }
        }
    }

    const int aAct = g.act - 1;
#pragma unroll
    for (int ni = 0; ni < 4; ni++) {
        int c = n0 + wn * 32 + ni * 8 + t4 * 2;
        float b0 = 0.0f, b1 = 0.0f;
        if (full) { b0 = g.bias[c]; b1 = g.bias[c + 1]; }
#pragma unroll
        for (int mi = 0; mi < 2; mi++)
#pragma unroll
            for (int h = 0; h < 2; h++) {
                int m = m0 + wm * 32 + mi * 16 + grp + h * 8;
                if (m < g.M) {
                    float v0 = acc[mi][ni][h * 2 + 0] + b0;
                    float v1 = acc[mi][ni][h * 2 + 1] + b1;
                    if (full && aAct >= 0) { v0 = actf(aAct, v0); v1 = actf(aAct, v1); }
                    *(float2*)(Cp + (long)m * g.ldc + c) = make_float2(v0, v1);
                }
            }
    }
}

// ---------------- softmax + top-k + routing (register-resident, 2 syncs) -----
__global__ __launch_bounds__(256) void route_k(const float* scores, const float* sbias,
                                               const float* temp,
                                               float* w, int* prei, int* mlpi, int* posti,
                                               int* cnt, int* rows) {
    const int t = blockIdx.x, tid = threadIdx.x;
    const int wid = tid >> 5, lane = tid & 31;
    __shared__ float ws1[8], ws2[8];
    __shared__ float cval[64];
    __shared__ int   cidx[64];

    const float invT = 1.0f / temp[0];
    const long TN = (long)T * NSCORE;

    float v[16];
    const int baseIdx = wid * 512 + lane;
#pragma unroll
    for (int j = 0; j < 16; j++) {
        int idx = baseIdx + 32 * j;
        long off = (long)t * NSCORE + idx;
        v[j] = (scores[off] + scores[TN + off] + sbias[idx]) * invT;
    }

    float mx = v[0];
#pragma unroll
    for (int j = 1; j < 16; j++) mx = fmaxf(mx, v[j]);
    mx = wmax(mx);
    if (lane == 0) ws1[wid] = mx;
    __syncthreads();
    float gmax = ws1[0];
#pragma unroll
    for (int i = 1; i < 8; i++) gmax = fmaxf(gmax, ws1[i]);

    float sum = 0.0f;
#pragma unroll
    for (int j = 0; j < 16; j++) sum += expf(v[j] - gmax);
    sum = wsum(sum);
    if (lane == 0) ws2[wid] = sum;

#pragma unroll
    for (int k = 0; k < TOPK; k++) {
        float bv = -3.4e38f; int bi = NSCORE;
#pragma unroll
        for (int j = 0; j < 16; j++) {
            if (v[j] > bv) { bv = v[j]; bi = baseIdx + 32 * j; }
        }
#pragma unroll
        for (int o = 16; o; o >>= 1) {
            float ov = __shfl_xor_sync(0xffffffffu, bv, o);
            int   oi = __shfl_xor_sync(0xffffffffu, bi, o);
            if (ov > bv || (ov == bv && oi < bi)) { bv = ov; bi = oi; }
        }
        if (lane == 0) { cval[wid * 8 + k] = bv; cidx[wid * 8 + k] = bi; }
        if ((bi & 31) == lane) v[(bi >> 5) & 15] = -3.4e38f;
    }
    __syncthreads();

    float gsum = ws2[0];
#pragma unroll
    for (int i = 1; i < 8; i++) gsum += ws2[i];

    if (wid == 0) {
        float cv0 = cval[lane], cv1 = cval[lane + 32];
        int   ci0 = cidx[lane], ci1 = cidx[lane + 32];
        float myv = 0.0f; int myi = 0;
#pragma unroll
        for (int k = 0; k < TOPK; k++) {
            float bv; int bi;
            if (cv0 > cv1 || (cv0 == cv1 && ci0 < ci1)) { bv = cv0; bi = ci0; }
            else                                        { bv = cv1; bi = ci1; }
#pragma unroll
            for (int o = 16; o; o >>= 1) {
                float ov = __shfl_xor_sync(0xffffffffu, bv, o);
                int   oi = __shfl_xor_sync(0xffffffffu, bi, o);
                if (ov > bv || (ov == bv && oi < bi)) { bv = ov; bi = oi; }
            }
            if (lane == k) { myv = bv; myi = bi; }
            if (ci0 == bi) cv0 = -3.4e38f;
            if (ci1 == bi) cv1 = -3.4e38f;
        }
        if (lane < TOPK) {
            float prob = expf(myv - gmax) / gsum;
            float ww = (prob >= 1e-6f) ? prob : 0.0f;
            int pair = t * TOPK + lane;
            int pe = myi >> 8, rem = myi & 255, me = rem >> 4, oe = rem & 15;
            prei[pair] = pe; mlpi[pair] = me; posti[pair] = oe; w[pair] = ww;
            int s0 = atomicAdd(&cnt[pe], 1);       rows[pe * NPAIR + s0] = pair;
            int s1 = atomicAdd(&cnt[16 + me], 1);  rows[(16 + me) * NPAIR + s1] = pair;
            int s2 = atomicAdd(&cnt[32 + oe], 1);  rows[(32 + oe) * NPAIR + s2] = pair;
        }
    }
}

// ---------------- pre: sum 2 partials + bias + LN + act ----------------------
__global__ __launch_bounds__(256) void prelnact_k(const float* U, const int* prei,
                                                  const float* pbias,
                                                  const float* g, const float* b, float* X) {
    const int warp = threadIdx.x >> 5, lane = threadIdx.x & 31;
    const int p = blockIdx.x * 8 + warp;
    const int e = prei[p];
    float u[16];
#pragma unroll
    for (int j = 0; j < 16; j++) {
        int idx = lane + 32 * j;
        u[j] = U[p * D + idx] + U[(long)NPAIR * D + p * D + idx] + pbias[e * D + idx];
    }

    float s = 0.0f;
#pragma unroll
    for (int j = 0; j < 16; j++) s += u[j];
    const float mean = wsum(s) * (1.0f / D);

    float v = 0.0f;
#pragma unroll
    for (int j = 0; j < 16; j++) { float d = u[j] - mean; v += d * d; }
    const float rstd = rsqrtf(wsum(v) * (1.0f / D) + 1e-5f);

    const int a = e & 3;
#pragma unroll
    for (int j = 0; j < 16; j++) {
        int idx = lane + 32 * j;
        float val = (u[j] - mean) * rstd * g[e * D + idx] + b[e * D + idx];
        X[p * D + idx] = actf(a, val);
    }
}

// ---------------- mlp2: sum 4 partials + bias --------------------------------
__global__ __launch_bounds__(256) void addy_k(const float* Y4, const int* mlpi,
                                              const float* b2, float* y) {
    const int warp = threadIdx.x >> 5, lane = threadIdx.x & 31;
    const int p = blockIdx.x * 8 + warp;
    const int e = mlpi[p];
#pragma unroll
    for (int j = 0; j < 16; j++) {
        int idx = lane + 32 * j;
        long off = (long)p * D + idx;
        float s = Y4[off] + Y4[(long)NPAIR * D + off]
                + Y4[2L * NPAIR * D + off] + Y4[3L * NPAIR * D + off]
                + b2[e * D + idx];
        y[off] = s;
    }
}

// ---------------- post: sum 2 partials + bias + LN + weighted reduce ---------
__global__ __launch_bounds__(256) void final_k(const float* Z, const int* posti, const float* w,
                                               const float* pbias,
                                               const float* g, const float* b, float* out) {
    const int t = blockIdx.x, tid = threadIdx.x;
    const int warp = tid >> 5, lane = tid & 31;
    __shared__ float sacc[8][D];

    const int pair = t * TOPK + warp;
    const int e = posti[pair];
    const float ww = w[pair];
    float z[16];
#pragma unroll
    for (int j = 0; j < 16; j++) {
        int idx = lane + 32 * j;
        z[j] = Z[(long)pair * D + idx] + Z[(long)NPAIR * D + (long)pair * D + idx]
             + pbias[e * D + idx];
    }

    if ((e & 1) == 0) {
        float s = 0.0f;
#pragma unroll
        for (int j = 0; j < 16; j++) s += z[j];
        const float mean = wsum(s) * (1.0f / D);
        float v = 0.0f;
#pragma unroll
        for (int j = 0; j < 16; j++) { float d = z[j] - mean; v += d * d; }
        const float rstd = rsqrtf(wsum(v) * (1.0f / D) + 1e-5f);
#pragma unroll
        for (int j = 0; j < 16; j++) {
            int idx = lane + 32 * j;
            z[j] = (z[j] - mean) * rstd * g[e * D + idx] + b[e * D + idx];
        }
    }
#pragma unroll
    for (int j = 0; j < 16; j++) sacc[warp][lane + 32 * j] = ww * z[j];
    __syncthreads();

    for (int i = tid; i < D; i += 256) {
        float s = 0.0f;
#pragma unroll
        for (int k = 0; k < 8; k++) s += sacc[k][i];
        out[t * D + i] = s;
    }
}

// ---------------- launch -----------------------------------------------------
extern "C" void kernel_launch(void* const* d_in, const int* in_sizes, int n_in,
                              void* d_out, int out_size) {
    const float* x       = (const float*)d_in[0];
    const float* r_w1    = (const float*)d_in[1];
    const float* r_b1    = (const float*)d_in[2];
    const float* r_w2    = (const float*)d_in[3];
    const float* r_b2    = (const float*)d_in[4];
    const float* r_w3    = (const float*)d_in[5];
    const float* r_b3    = (const float*)d_in[6];
    const float* temp    = (const float*)d_in[7];
    const float* pre_w   = (const float*)d_in[8];
    const float* pre_b   = (const float*)d_in[9];
    const float* pre_g   = (const float*)d_in[10];
    const float* pre_be  = (const float*)d_in[11];
    const float* mlp_w1  = (const float*)d_in[12];
    const float* mlp_b1  = (const float*)d_in[13];
    const float* mlp_w2  = (const float*)d_in[14];
    const float* mlp_b2  = (const float*)d_in[15];
    const float* post_w  = (const float*)d_in[16];
    const float* post_b  = (const float*)d_in[17];
    const float* post_g  = (const float*)d_in[18];
    const float* post_be = (const float*)d_in[19];
    float* out = (float*)d_out;

    float *h1, *h2, *sc, *preu, *xin, *hmid, *y4, *y, *z, *w;
    int *prei, *mlpi, *posti, *cnt, *rows;
    cudaGetSymbolAddress((void**)&h1, g_h1);
    cudaGetSymbolAddress((void**)&h2, g_h2);
    cudaGetSymbolAddress((void**)&sc, g_scores);
    cudaGetSymbolAddress((void**)&preu, g_preu);
    cudaGetSymbolAddress((void**)&xin, g_xin);
    cudaGetSymbolAddress((void**)&hmid, g_hmid);
    cudaGetSymbolAddress((void**)&y4, g_y4);
    cudaGetSymbolAddress((void**)&y, g_y);
    cudaGetSymbolAddress((void**)&z, g_z);
    cudaGetSymbolAddress((void**)&w, g_w);
    cudaGetSymbolAddress((void**)&prei, g_prei);
    cudaGetSymbolAddress((void**)&mlpi, g_mlpi);
    cudaGetSymbolAddress((void**)&posti, g_posti);
    cudaGetSymbolAddress((void**)&cnt, g_cnt);
    cudaGetSymbolAddress((void**)&rows, g_rows);

    // router fc1 (also zeroes routing counters in block 0)
    {
        GArgs a = {x, D, r_w1, 0, 512, r_b1, 0, h1, 512,
                   T, 512, 512, nullptr, nullptr, 0, 0, 0, 1, 0, cnt};
        rgemm_k<<<dim3(8, 2, 1), 256>>>(a);
    }
    {
        GArgs a = {h1, 512, r_w2, 0, 256, r_b2, 0, h2, 256,
                   T, 256, 512, nullptr, nullptr, 0, 0, 0, 1, 0, nullptr};
        rgemm_k<<<dim3(4, 2, 1), 256>>>(a);
    }
    // fc3: split-K=2 (grid z), partials summed (with bias) inside route_k
    {
        GArgs a = {h2, 256, r_w3, 0, NSCORE, r_b3, 0, sc, NSCORE,
                   T, NSCORE, 128, nullptr, nullptr, 0, 0, 0, 0,
                   (long)T * NSCORE, nullptr};
        rgemm_k<<<dim3(64, 2, 2), 256>>>(a);
    }

    route_k<<<T, 256>>>(sc, r_b3, temp, w, prei, mlpi, posti, cnt, rows);

    // pre: split-K=2, S=4 (short K-stream)
    {
        GArgs a = {x, D, pre_w, (long)D * D, D, pre_b, D, preu, D,
                   NPAIR, D, D, rows, cnt, 3, 0, 0, 0, (long)NPAIR * D, nullptr};
        tgemm_k<2, 4><<<dim3(16, 6, NEXP), 64>>>(a);
    }
    prelnact_k<<<NPAIR / 8, 256>>>(preu, prei, pre_b, pre_g, pre_be, xin);

    // mlp1: fused bias+act, S=5 (deep pipeline for long K-stream weight traffic)
    {
        GArgs a = {xin, D, mlp_w1, (long)D * MAXH, MAXH, mlp_b1, MAXH, hmid, MAXH,
                   NPAIR, MAXH, D, rows + 16 * NPAIR, cnt + 16, 0, 1, 0, 5, 0, nullptr};
        tgemm_k<1, 5><<<dim3(40, 6, NEXP), 64>>>(a);
    }
    // mlp2: split-K=4, S=5
    {
        GArgs a = {hmid, MAXH, mlp_w2, (long)MAXH * D, D, mlp_b2, D, y4, D,
                   NPAIR, D, MAXH, rows + 16 * NPAIR, cnt + 16, 0, 0, 1, 0,
                   (long)NPAIR * D, nullptr};
        tgemm_k<4, 5><<<dim3(32, 6, NEXP), 64>>>(a);
    }
    addy_k<<<NPAIR / 8, 256>>>(y4, mlpi, mlp_b2, y);

    // post: split-K=2, S=4
    {
        GArgs a = {y, D, post_w, (long)D * D, D, post_b, D, z, D,
                   NPAIR, D, D, rows + 32 * NPAIR, cnt + 32, 0, 0, 0, 0,
                   (long)NPAIR * D, nullptr};
        tgemm_k<2, 4><<<dim3(16, 6, NEXP), 64>>>(a);
    }

    final_k<<<T, 256>>>(z, posti, w, post_b, post_g, post_be, out);
}

// round 15
// speedup vs baseline: 1.0594x; 1.0594x over previous
#include <cuda_runtime.h>
#include <math.h>
#include <stdint.h>

#define D      512
#define T      256
#define TOPK   8
#define NPAIR  2048
#define NEXP   16
#define MAXH   2560
#define NSCORE 4096

// ---------------- scratch ----------------------------------------------------
__device__ float g_h1[T * D];
__device__ float g_h2[T * 256];
__device__ float g_scores[2 * T * NSCORE];   // 2 split-K partials (fc3)
__device__ float g_preu[2 * NPAIR * D];      // 2 split-K partials
__device__ float g_xin[NPAIR * D];
__device__ float g_hmid[NPAIR * MAXH];
__device__ float g_y[NPAIR * D];             // mlp2 output (bias-init + atomic acc)
__device__ float g_z[2 * NPAIR * D];         // 2 split-K partials (post)
__device__ float g_w[NPAIR];
__device__ int   g_prei[NPAIR];
__device__ int   g_mlpi[NPAIR];
__device__ int   g_posti[NPAIR];
__device__ int   g_cnt[48];
__device__ int   g_rows[48 * NPAIR];

// ---------------- helpers ----------------------------------------------------
__device__ __forceinline__ float actf(int a, float v) {
    switch (a) {
        case 0: return 0.5f * v * (1.0f + erff(v * 0.7071067811865476f));
        case 1: return fmaxf(v, 0.0f);
        case 2: return tanhf(v);
        default: return v / (1.0f + expf(-v));
    }
}

__device__ __forceinline__ unsigned f2tf32(float f) {
    unsigned r;
    asm("cvt.rna.tf32.f32 %0, %1;" : "=r"(r) : "f"(f));
    return r;
}

__device__ __forceinline__ uint32_t sptr(const void* p) {
    return (uint32_t)__cvta_generic_to_shared(p);
}

__device__ __forceinline__ void cpa16(uint32_t d, const float* s, bool pred) {
    int sz = pred ? 16 : 0;
    asm volatile("cp.async.cg.shared.global [%0], [%1], 16, %2;"
                 :: "r"(d), "l"(s), "r"(sz));
}

__device__ __forceinline__ float wsum(float v) {
#pragma unroll
    for (int o = 16; o; o >>= 1) v += __shfl_xor_sync(0xffffffffu, v, o);
    return v;
}
__device__ __forceinline__ float wmax(float v) {
#pragma unroll
    for (int o = 16; o; o >>= 1) v = fmaxf(v, __shfl_xor_sync(0xffffffffu, v, o));
    return v;
}

#define MMA_TF32(c, a0, a1, a2, a3, b0, b1)                                      \
    asm volatile("mma.sync.aligned.m16n8k8.row.col.f32.tf32.tf32.f32 "           \
                 "{%0,%1,%2,%3}, {%4,%5,%6,%7}, {%8,%9}, {%0,%1,%2,%3};"         \
                 : "+f"((c)[0]), "+f"((c)[1]), "+f"((c)[2]), "+f"((c)[3])        \
                 : "r"(a0), "r"(a1), "r"(a2), "r"(a3), "r"(b0), "r"(b1))

struct GArgs {
    const float* A; int lda;
    const float* B; long bStride; int ldb;
    const float* bias; int biasStride;
    float* C; int ldc;
    int M, N, K;
    const int* rows; const int* cnt;
    int gshift;
    int varN, varK;
    int act;            // 0 none, 1..4 fixed (act-1), 5 per-expert e&3
    long cStride;       // split-K partial-buffer stride (elements)
    int* zcnt;          // if non-null: block (0,0,0) zeroes 48 counters
    int red;            // split-K epilogue: 1 = atomicAdd into shared C buffer
};

// ---------------- tf32 grouped GEMM (experts), split-K capable ---------------
// BM=32, BN=64; 64 threads = 2 warps; warp tile 32x32; S-stage cp.async.
template<int SPLIT, int S>
__global__ __launch_bounds__(64) void tgemm_k(GArgs g) {
    constexpr int BM  = 32;
    constexpr int BN  = 64;
    constexpr int MI  = 2;
    constexpr int NI  = 4;
    constexpr int BNP = BN + 8;

    const int e  = blockIdx.z;
    const int Me = g.cnt[e];
    if (Me == 0) return;
    const int he = 512 * (2 + (e >> 2));
    const int Ne = g.varN ? he : g.N;
    const int Ke = g.varK ? he : g.K;

    const int ntiles = gridDim.x / SPLIT;
    const int slice  = blockIdx.x / ntiles;
    const int n0     = (blockIdx.x % ntiles) * BN;
    if (n0 >= Ne) return;

    const int Ksl   = Ke / SPLIT;
    const int kbase = slice * Ksl;
    const int KT    = Ksl >> 4;

    float* Cp = g.C + (long)slice * g.cStride;

    const float* Bp = g.B + (long)e * g.bStride;
    const int*   rl = g.rows + e * NPAIR;

    __shared__ float As[S][BM][20];
    __shared__ float Bs[S][16][BNP];

    const int tid = threadIdx.x, lane = tid & 31;
    const int wn = tid >> 5;
    const int grp = lane >> 2, t4 = lane & 3;
    const int a_row = tid >> 1;
    const int aq    = (tid & 1) * 2;

    const int aAct = (g.act == 5) ? (e & 3) : (g.act - 1);

    for (int m0 = blockIdx.y * BM; m0 < Me; m0 += gridDim.y * BM) {
        const bool mv = (m0 + a_row) < Me;
        long arow = 0;
        if (mv) arow = (long)(rl[m0 + a_row] >> g.gshift);
        const float* Ap = g.A + arow * (long)g.lda + kbase;

        int crow[MI * 2];
#pragma unroll
        for (int mi = 0; mi < MI; mi++)
#pragma unroll
            for (int h = 0; h < 2; h++) {
                int m = m0 + mi * 16 + grp + h * 8;
                crow[mi * 2 + h] = (m < Me) ? rl[m] : -1;
            }

        float acc[MI][NI][4];
#pragma unroll
        for (int mi = 0; mi < MI; mi++)
#pragma unroll
            for (int ni = 0; ni < NI; ni++)
#pragma unroll
                for (int c = 0; c < 4; c++) acc[mi][ni][c] = 0.0f;

        auto loadStage = [&](int s, int kt) {
            int k0 = kt << 4;
#pragma unroll
            for (int i = 0; i < 2; i++)
                cpa16(sptr(&As[s][a_row][(aq + i) * 4]), Ap + k0 + (aq + i) * 4, mv);
#pragma unroll
            for (int i = 0; i < 4; i++) {
                int idx = tid + i * 64;
                int r = idx >> 4, col = (idx & 15) * 4;
                cpa16(sptr(&Bs[s][r][col]),
                      Bp + (long)(kbase + k0 + r) * g.ldb + n0 + col, true);
            }
            asm volatile("cp.async.commit_group;");
        };

#pragma unroll
        for (int s = 0; s < S - 1; s++) {
            if (s < KT) loadStage(s, s);
            else        asm volatile("cp.async.commit_group;");
        }

        for (int kt = 0; kt < KT; kt++) {
            asm volatile("cp.async.wait_group %0;" :: "n"(S - 2));
            __syncthreads();
            const int buf = kt % S;

            if (kt + S - 1 < KT) loadStage((kt + S - 1) % S, kt + S - 1);
            else                 asm volatile("cp.async.commit_group;");

#pragma unroll
            for (int ks = 0; ks < 2; ks++) {
                const int kk = ks * 8;
                unsigned a[MI][4], b[NI][2];
#pragma unroll
                for (int mi = 0; mi < MI; mi++) {
                    int mr = mi * 16 + grp;
                    a[mi][0] = f2tf32(As[buf][mr][kk + t4]);
                    a[mi][1] = f2tf32(As[buf][mr + 8][kk + t4]);
                    a[mi][2] = f2tf32(As[buf][mr][kk + t4 + 4]);
                    a[mi][3] = f2tf32(As[buf][mr + 8][kk + t4 + 4]);
                }
#pragma unroll
                for (int ni = 0; ni < NI; ni++) {
                    int nc = wn * 32 + ni * 8 + grp;
                    b[ni][0] = f2tf32(Bs[buf][kk + t4][nc]);
                    b[ni][1] = f2tf32(Bs[buf][kk + t4 + 4][nc]);
                }
#pragma unroll
                for (int mi = 0; mi < MI; mi++)
#pragma unroll
                    for (int ni = 0; ni < NI; ni++)
                        MMA_TF32(acc[mi][ni], a[mi][0], a[mi][1], a[mi][2], a[mi][3],
                                 b[ni][0], b[ni][1]);
            }
        }

#pragma unroll
        for (int ni = 0; ni < NI; ni++) {
            int c = n0 + wn * 32 + ni * 8 + t4 * 2;
            float b0 = 0.0f, b1 = 0.0f;
            if (SPLIT == 1) {
                const float* bias = g.bias + (long)e * g.biasStride;
                b0 = bias[c]; b1 = bias[c + 1];
            }
#pragma unroll
            for (int mi = 0; mi < MI; mi++)
#pragma unroll
                for (int h = 0; h < 2; h++) {
                    int cr = crow[mi * 2 + h];
                    if (cr >= 0) {
                        float v0 = acc[mi][ni][h * 2 + 0] + b0;
                        float v1 = acc[mi][ni][h * 2 + 1] + b1;
                        if (SPLIT == 1 && aAct >= 0) { v0 = actf(aAct, v0); v1 = actf(aAct, v1); }
                        if (SPLIT > 1 && g.red) {
                            atomicAdd(Cp + (long)cr * g.ldc + c,     v0);
                            atomicAdd(Cp + (long)cr * g.ldc + c + 1, v1);
                        } else {
                            *(float2*)(Cp + (long)cr * g.ldc + c) = make_float2(v0, v1);
                        }
                    }
                }
        }
        asm volatile("cp.async.wait_group 0;");
        __syncthreads();
    }
}

// ---------------- router GEMM: split-tf32 (hi/lo), optional split-K ----------
__global__ __launch_bounds__(256) void rgemm_k(GArgs g) {
    const int n0 = blockIdx.x * 64;
    const int m0 = blockIdx.y * 128;
    if (n0 >= g.N) return;
    const int slice = blockIdx.z;

    if (g.zcnt && blockIdx.x == 0 && blockIdx.y == 0 && slice == 0 && threadIdx.x < 48)
        g.zcnt[threadIdx.x] = 0;

    __shared__ unsigned AsH[128][20], AsL[128][20];
    __shared__ unsigned BsH[16][72], BsL[16][72];

    const int tid = threadIdx.x, warp = tid >> 5, lane = tid & 31;
    const int grp = lane >> 2, t4 = lane & 3;
    const int wm = warp >> 1, wn = warp & 1;
    const int a_row = tid >> 1;
    const int aq = (tid & 1) * 2;
    const int bk = tid >> 4, cb = (tid & 15) * 4;

    const bool mv = (m0 + a_row) < g.M;
    const float* Ap = g.A + (long)(m0 + a_row) * g.lda + (long)slice * g.K;
    const float* Bp = g.B + (long)slice * g.K * g.ldb;
    float* Cp = g.C + (long)slice * g.cStride;
    const bool full = (g.cStride == 0);

    float acc[2][4][4];
#pragma unroll
    for (int mi = 0; mi < 2; mi++)
#pragma unroll
        for (int ni = 0; ni < 4; ni++)
#pragma unroll
            for (int c = 0; c < 4; c++) acc[mi][ni][c] = 0.0f;

    float4 av[2], bv;
    auto ldreg = [&](int k0) {
#pragma unroll
        for (int i = 0; i < 2; i++)
            av[i] = mv ? *(const float4*)(Ap + k0 + (aq + i) * 4)
                       : make_float4(0.f, 0.f, 0.f, 0.f);
        bv = *(const float4*)(Bp + (long)(k0 + bk) * g.ldb + n0 + cb);
    };

    const int KT = g.K >> 4;
    ldreg(0);
    for (int kt = 0; kt < KT; kt++) {
        __syncthreads();
#pragma unroll
        for (int i = 0; i < 2; i++) {
            float vv[4] = {av[i].x, av[i].y, av[i].z, av[i].w};
            uint4 uh, ul;
            unsigned* ph = &uh.x; unsigned* pl = &ul.x;
#pragma unroll
            for (int c = 0; c < 4; c++) {
                unsigned hb = f2tf32(vv[c]);
                ph[c] = hb;
                pl[c] = f2tf32(vv[c] - __uint_as_float(hb));
            }
            *(uint4*)&AsH[a_row][(aq + i) * 4] = uh;
            *(uint4*)&AsL[a_row][(aq + i) * 4] = ul;
        }
        {
            float vv[4] = {bv.x, bv.y, bv.z, bv.w};
            uint4 uh, ul;
            unsigned* ph = &uh.x; unsigned* pl = &ul.x;
#pragma unroll
            for (int c = 0; c < 4; c++) {
                unsigned hb = f2tf32(vv[c]);
                ph[c] = hb;
                pl[c] = f2tf32(vv[c] - __uint_as_float(hb));
            }
            *(uint4*)&BsH[bk][cb] = uh;
            *(uint4*)&BsL[bk][cb] = ul;
        }
        __syncthreads();

        if (kt + 1 < KT) ldreg((kt + 1) << 4);

#pragma unroll
        for (int ks = 0; ks < 2; ks++) {
            const int kk = ks * 8;
            unsigned ah[2][4], al[2][4], bh[4][2], bl[4][2];
#pragma unroll
            for (int mi = 0; mi < 2; mi++) {
                int mr = wm * 32 + mi * 16 + grp;
                ah[mi][0] = AsH[mr][kk + t4];     al[mi][0] = AsL[mr][kk + t4];
                ah[mi][1] = AsH[mr + 8][kk + t4]; al[mi][1] = AsL[mr + 8][kk + t4];
                ah[mi][2] = AsH[mr][kk + t4 + 4]; al[mi][2] = AsL[mr][kk + t4 + 4];
                ah[mi][3] = AsH[mr + 8][kk + t4 + 4]; al[mi][3] = AsL[mr + 8][kk + t4 + 4];
            }
#pragma unroll
            for (int ni = 0; ni < 4; ni++) {
                int nc = wn * 32 + ni * 8 + grp;
                bh[ni][0] = BsH[kk + t4][nc];     bl[ni][0] = BsL[kk + t4][nc];
                bh[ni][1] = BsH[kk + t4 + 4][nc]; bl[ni][1] = BsL[kk + t4 + 4][nc];
            }
#pragma unroll
            for (int mi = 0; mi < 2; mi++)
#pragma unroll
                for (int ni = 0; ni < 4; ni++) {
                    MMA_TF32(acc[mi][ni], ah[mi][0], ah[mi][1], ah[mi][2], ah[mi][3],
                             bh[ni][0], bh[ni][1]);
                    MMA_TF32(acc[mi][ni], ah[mi][0], ah[mi][1], ah[mi][2], ah[mi][3],
                             bl[ni][0], bl[ni][1]);
                    MMA_TF32(acc[mi][ni], al[mi][0], al[mi][1], al[mi][2], al[mi][3],
                             bh[ni][0], bh[ni][1]);
                }
        }
    }

    const int aAct = g.act - 1;
#pragma unroll
    for (int ni = 0; ni < 4; ni++) {
        int c = n0 + wn * 32 + ni * 8 + t4 * 2;
        float b0 = 0.0f, b1 = 0.0f;
        if (full) { b0 = g.bias[c]; b1 = g.bias[c + 1]; }
#pragma unroll
        for (int mi = 0; mi < 2; mi++)
#pragma unroll
            for (int h = 0; h < 2; h++) {
                int m = m0 + wm * 32 + mi * 16 + grp + h * 8;
                if (m < g.M) {
                    float v0 = acc[mi][ni][h * 2 + 0] + b0;
                    float v1 = acc[mi][ni][h * 2 + 1] + b1;
                    if (full && aAct >= 0) { v0 = actf(aAct, v0); v1 = actf(aAct, v1); }
                    *(float2*)(Cp + (long)m * g.ldc + c) = make_float2(v0, v1);
                }
            }
    }
}

// ---------------- softmax + top-k + routing (register-resident, 2 syncs) -----
__global__ __launch_bounds__(256) void route_k(const float* scores, const float* sbias,
                                               const float* temp,
                                               float* w, int* prei, int* mlpi, int* posti,
                                               int* cnt, int* rows) {
    const int t = blockIdx.x, tid = threadIdx.x;
    const int wid = tid >> 5, lane = tid & 31;
    __shared__ float ws1[8], ws2[8];
    __shared__ float cval[64];
    __shared__ int   cidx[64];

    const float invT = 1.0f / temp[0];
    const long TN = (long)T * NSCORE;

    float v[16];
    const int baseIdx = wid * 512 + lane;
#pragma unroll
    for (int j = 0; j < 16; j++) {
        int idx = baseIdx + 32 * j;
        long off = (long)t * NSCORE + idx;
        v[j] = (scores[off] + scores[TN + off] + sbias[idx]) * invT;
    }

    float mx = v[0];
#pragma unroll
    for (int j = 1; j < 16; j++) mx = fmaxf(mx, v[j]);
    mx = wmax(mx);
    if (lane == 0) ws1[wid] = mx;
    __syncthreads();
    float gmax = ws1[0];
#pragma unroll
    for (int i = 1; i < 8; i++) gmax = fmaxf(gmax, ws1[i]);

    float sum = 0.0f;
#pragma unroll
    for (int j = 0; j < 16; j++) sum += expf(v[j] - gmax);
    sum = wsum(sum);
    if (lane == 0) ws2[wid] = sum;

#pragma unroll
    for (int k = 0; k < TOPK; k++) {
        float bv = -3.4e38f; int bi = NSCORE;
#pragma unroll
        for (int j = 0; j < 16; j++) {
            if (v[j] > bv) { bv = v[j]; bi = baseIdx + 32 * j; }
        }
#pragma unroll
        for (int o = 16; o; o >>= 1) {
            float ov = __shfl_xor_sync(0xffffffffu, bv, o);
            int   oi = __shfl_xor_sync(0xffffffffu, bi, o);
            if (ov > bv || (ov == bv && oi < bi)) { bv = ov; bi = oi; }
        }
        if (lane == 0) { cval[wid * 8 + k] = bv; cidx[wid * 8 + k] = bi; }
        if ((bi & 31) == lane) v[(bi >> 5) & 15] = -3.4e38f;
    }
    __syncthreads();

    float gsum = ws2[0];
#pragma unroll
    for (int i = 1; i < 8; i++) gsum += ws2[i];

    if (wid == 0) {
        float cv0 = cval[lane], cv1 = cval[lane + 32];
        int   ci0 = cidx[lane], ci1 = cidx[lane + 32];
        float myv = 0.0f; int myi = 0;
#pragma unroll
        for (int k = 0; k < TOPK; k++) {
            float bv; int bi;
            if (cv0 > cv1 || (cv0 == cv1 && ci0 < ci1)) { bv = cv0; bi = ci0; }
            else                                        { bv = cv1; bi = ci1; }
#pragma unroll
            for (int o = 16; o; o >>= 1) {
                float ov = __shfl_xor_sync(0xffffffffu, bv, o);
                int   oi = __shfl_xor_sync(0xffffffffu, bi, o);
                if (ov > bv || (ov == bv && oi < bi)) { bv = ov; bi = oi; }
            }
            if (lane == k) { myv = bv; myi = bi; }
            if (ci0 == bi) cv0 = -3.4e38f;
            if (ci1 == bi) cv1 = -3.4e38f;
        }
        if (lane < TOPK) {
            float prob = expf(myv - gmax) / gsum;
            float ww = (prob >= 1e-6f) ? prob : 0.0f;
            int pair = t * TOPK + lane;
            int pe = myi >> 8, rem = myi & 255, me = rem >> 4, oe = rem & 15;
            prei[pair] = pe; mlpi[pair] = me; posti[pair] = oe; w[pair] = ww;
            int s0 = atomicAdd(&cnt[pe], 1);       rows[pe * NPAIR + s0] = pair;
            int s1 = atomicAdd(&cnt[16 + me], 1);  rows[(16 + me) * NPAIR + s1] = pair;
            int s2 = atomicAdd(&cnt[32 + oe], 1);  rows[(32 + oe) * NPAIR + s2] = pair;
        }
    }
}

// ---------------- pre: sum 2 partials + bias + LN + act; also init y=bias ----
__global__ __launch_bounds__(256) void prelnact_k(const float* U, const int* prei,
                                                  const float* pbias,
                                                  const float* g, const float* b, float* X,
                                                  const int* mlpi, const float* mb2, float* y) {
    const int warp = threadIdx.x >> 5, lane = threadIdx.x & 31;
    const int p = blockIdx.x * 8 + warp;
    const int e = prei[p];
    const int e2 = mlpi[p];
    float u[16];
#pragma unroll
    for (int j = 0; j < 16; j++) {
        int idx = lane + 32 * j;
        u[j] = U[p * D + idx] + U[(long)NPAIR * D + p * D + idx] + pbias[e * D + idx];
        y[(long)p * D + idx] = mb2[e2 * D + idx];   // bias-init for mlp2 atomic acc
    }

    float s = 0.0f;
#pragma unroll
    for (int j = 0; j < 16; j++) s += u[j];
    const float mean = wsum(s) * (1.0f / D);

    float v = 0.0f;
#pragma unroll
    for (int j = 0; j < 16; j++) { float d = u[j] - mean; v += d * d; }
    const float rstd = rsqrtf(wsum(v) * (1.0f / D) + 1e-5f);

    const int a = e & 3;
#pragma unroll
    for (int j = 0; j < 16; j++) {
        int idx = lane + 32 * j;
        float val = (u[j] - mean) * rstd * g[e * D + idx] + b[e * D + idx];
        X[p * D + idx] = actf(a, val);
    }
}

// ---------------- post: sum 2 partials + bias + LN + weighted reduce ---------
__global__ __launch_bounds__(256) void final_k(const float* Z, const int* posti, const float* w,
                                               const float* pbias,
                                               const float* g, const float* b, float* out) {
    const int t = blockIdx.x, tid = threadIdx.x;
    const int warp = tid >> 5, lane = tid & 31;
    __shared__ float sacc[8][D];

    const int pair = t * TOPK + warp;
    const int e = posti[pair];
    const float ww = w[pair];
    float z[16];
#pragma unroll
    for (int j = 0; j < 16; j++) {
        int idx = lane + 32 * j;
        z[j] = Z[(long)pair * D + idx] + Z[(long)NPAIR * D + (long)pair * D + idx]
             + pbias[e * D + idx];
    }

    if ((e & 1) == 0) {
        float s = 0.0f;
#pragma unroll
        for (int j = 0; j < 16; j++) s += z[j];
        const float mean = wsum(s) * (1.0f / D);
        float v = 0.0f;
#pragma unroll
        for (int j = 0; j < 16; j++) { float d = z[j] - mean; v += d * d; }
        const float rstd = rsqrtf(wsum(v) * (1.0f / D) + 1e-5f);
#pragma unroll
        for (int j = 0; j < 16; j++) {
            int idx = lane + 32 * j;
            z[j] = (z[j] - mean) * rstd * g[e * D + idx] + b[e * D + idx];
        }
    }
#pragma unroll
    for (int j = 0; j < 16; j++) sacc[warp][lane + 32 * j] = ww * z[j];
    __syncthreads();

    for (int i = tid; i < D; i += 256) {
        float s = 0.0f;
#pragma unroll
        for (int k = 0; k < 8; k++) s += sacc[k][i];
        out[t * D + i] = s;
    }
}

// ---------------- launch -----------------------------------------------------
extern "C" void kernel_launch(void* const* d_in, const int* in_sizes, int n_in,
                              void* d_out, int out_size) {
    const float* x       = (const float*)d_in[0];
    const float* r_w1    = (const float*)d_in[1];
    const float* r_b1    = (const float*)d_in[2];
    const float* r_w2    = (const float*)d_in[3];
    const float* r_b2    = (const float*)d_in[4];
    const float* r_w3    = (const float*)d_in[5];
    const float* r_b3    = (const float*)d_in[6];
    const float* temp    = (const float*)d_in[7];
    const float* pre_w   = (const float*)d_in[8];
    const float* pre_b   = (const float*)d_in[9];
    const float* pre_g   = (const float*)d_in[10];
    const float* pre_be  = (const float*)d_in[11];
    const float* mlp_w1  = (const float*)d_in[12];
    const float* mlp_b1  = (const float*)d_in[13];
    const float* mlp_w2  = (const float*)d_in[14];
    const float* mlp_b2  = (const float*)d_in[15];
    const float* post_w  = (const float*)d_in[16];
    const float* post_b  = (const float*)d_in[17];
    const float* post_g  = (const float*)d_in[18];
    const float* post_be = (const float*)d_in[19];
    float* out = (float*)d_out;

    float *h1, *h2, *sc, *preu, *xin, *hmid, *y, *z, *w;
    int *prei, *mlpi, *posti, *cnt, *rows;
    cudaGetSymbolAddress((void**)&h1, g_h1);
    cudaGetSymbolAddress((void**)&h2, g_h2);
    cudaGetSymbolAddress((void**)&sc, g_scores);
    cudaGetSymbolAddress((void**)&preu, g_preu);
    cudaGetSymbolAddress((void**)&xin, g_xin);
    cudaGetSymbolAddress((void**)&hmid, g_hmid);
    cudaGetSymbolAddress((void**)&y, g_y);
    cudaGetSymbolAddress((void**)&z, g_z);
    cudaGetSymbolAddress((void**)&w, g_w);
    cudaGetSymbolAddress((void**)&prei, g_prei);
    cudaGetSymbolAddress((void**)&mlpi, g_mlpi);
    cudaGetSymbolAddress((void**)&posti, g_posti);
    cudaGetSymbolAddress((void**)&cnt, g_cnt);
    cudaGetSymbolAddress((void**)&rows, g_rows);

    // router fc1 (also zeroes routing counters in block 0)
    {
        GArgs a = {x, D, r_w1, 0, 512, r_b1, 0, h1, 512,
                   T, 512, 512, nullptr, nullptr, 0, 0, 0, 1, 0, cnt, 0};
        rgemm_k<<<dim3(8, 2, 1), 256>>>(a);
    }
    {
        GArgs a = {h1, 512, r_w2, 0, 256, r_b2, 0, h2, 256,
                   T, 256, 512, nullptr, nullptr, 0, 0, 0, 1, 0, nullptr, 0};
        rgemm_k<<<dim3(4, 2, 1), 256>>>(a);
    }
    // fc3: split-K=2 (grid z), partials summed (with bias) inside route_k
    {
        GArgs a = {h2, 256, r_w3, 0, NSCORE, r_b3, 0, sc, NSCORE,
                   T, NSCORE, 128, nullptr, nullptr, 0, 0, 0, 0,
                   (long)T * NSCORE, nullptr, 0};
        rgemm_k<<<dim3(64, 2, 2), 256>>>(a);
    }

    route_k<<<T, 256>>>(sc, r_b3, temp, w, prei, mlpi, posti, cnt, rows);

    // pre: split-K=2, S=4
    {
        GArgs a = {x, D, pre_w, (long)D * D, D, pre_b, D, preu, D,
                   NPAIR, D, D, rows, cnt, 3, 0, 0, 0, (long)NPAIR * D, nullptr, 0};
        tgemm_k<2, 4><<<dim3(16, 6, NEXP), 64>>>(a);
    }
    // pre LN + act; also initializes y = mlp_b2[mlpi] for mlp2 accumulation
    prelnact_k<<<NPAIR / 8, 256>>>(preu, prei, pre_b, pre_g, pre_be, xin,
                                   mlpi, mlp_b2, y);

    // mlp1: fused bias+act, S=3
    {
        GArgs a = {xin, D, mlp_w1, (long)D * MAXH, MAXH, mlp_b1, MAXH, hmid, MAXH,
                   NPAIR, MAXH, D, rows + 16 * NPAIR, cnt + 16, 0, 1, 0, 5, 0, nullptr, 0};
        tgemm_k<1, 3><<<dim3(40, 6, NEXP), 64>>>(a);
    }
    // mlp2: split-K=4, S=3, slices atomically accumulate into bias-initialized y
    {
        GArgs a = {hmid, MAXH, mlp_w2, (long)MAXH * D, D, mlp_b2, D, y, D,
                   NPAIR, D, MAXH, rows + 16 * NPAIR, cnt + 16, 0, 0, 1, 0,
                   0, nullptr, 1};
        tgemm_k<4, 3><<<dim3(32, 6, NEXP), 64>>>(a);
    }

    // post: split-K=2, S=4
    {
        GArgs a = {y, D, post_w, (long)D * D, D, post_b, D, z, D,
                   NPAIR, D, D, rows + 32 * NPAIR, cnt + 32, 0, 0, 0, 0,
                   (long)NPAIR * D, nullptr, 0};
        tgemm_k<2, 4><<<dim3(16, 6, NEXP), 64>>>(a);
    }

    final_k<<<T, 256>>>(z, posti, w, post_b, post_g, post_be, out);
}

// round 16
// speedup vs baseline: 1.1195x; 1.0568x over previous
#include <cuda_runtime.h>
#include <math.h>
#include <stdint.h>

#define D      512
#define T      256
#define TOPK   8
#define NPAIR  2048
#define NEXP   16
#define MAXH   2560
#define NSCORE 4096

// ---------------- scratch ----------------------------------------------------
__device__ float g_h1[2 * T * D];            // 2 split-K partials (fc1)
__device__ float g_h2[2 * T * 256];          // 2 split-K partials (fc2)
__device__ float g_scores[2 * T * NSCORE];   // 2 split-K partials (fc3)
__device__ float g_preu[2 * NPAIR * D];      // 2 split-K partials
__device__ float g_xin[NPAIR * D];
__device__ float g_hmid[NPAIR * MAXH];
__device__ float g_y[NPAIR * D];             // mlp2 output (bias-init + atomic acc)
__device__ float g_z[2 * NPAIR * D];         // 2 split-K partials (post)
__device__ float g_w[NPAIR];
__device__ int   g_prei[NPAIR];
__device__ int   g_mlpi[NPAIR];
__device__ int   g_posti[NPAIR];
__device__ int   g_cnt[48];
__device__ int   g_rows[48 * NPAIR];

// ---------------- helpers ----------------------------------------------------
__device__ __forceinline__ float actf(int a, float v) {
    switch (a) {
        case 0: return 0.5f * v * (1.0f + erff(v * 0.7071067811865476f));
        case 1: return fmaxf(v, 0.0f);
        case 2: return tanhf(v);
        default: return v / (1.0f + expf(-v));
    }
}

__device__ __forceinline__ unsigned f2tf32(float f) {
    unsigned r;
    asm("cvt.rna.tf32.f32 %0, %1;" : "=r"(r) : "f"(f));
    return r;
}

__device__ __forceinline__ uint32_t sptr(const void* p) {
    return (uint32_t)__cvta_generic_to_shared(p);
}

__device__ __forceinline__ void cpa16(uint32_t d, const float* s, bool pred) {
    int sz = pred ? 16 : 0;
    asm volatile("cp.async.cg.shared.global [%0], [%1], 16, %2;"
                 :: "r"(d), "l"(s), "r"(sz));
}

__device__ __forceinline__ float wsum(float v) {
#pragma unroll
    for (int o = 16; o; o >>= 1) v += __shfl_xor_sync(0xffffffffu, v, o);
    return v;
}
__device__ __forceinline__ float wmax(float v) {
#pragma unroll
    for (int o = 16; o; o >>= 1) v = fmaxf(v, __shfl_xor_sync(0xffffffffu, v, o));
    return v;
}

#define MMA_TF32(c, a0, a1, a2, a3, b0, b1)                                      \
    asm volatile("mma.sync.aligned.m16n8k8.row.col.f32.tf32.tf32.f32 "           \
                 "{%0,%1,%2,%3}, {%4,%5,%6,%7}, {%8,%9}, {%0,%1,%2,%3};"         \
                 : "+f"((c)[0]), "+f"((c)[1]), "+f"((c)[2]), "+f"((c)[3])        \
                 : "r"(a0), "r"(a1), "r"(a2), "r"(a3), "r"(b0), "r"(b1))

struct GArgs {
    const float* A; int lda;
    const float* B; long bStride; int ldb;
    const float* bias; int biasStride;
    float* C; int ldc;
    int M, N, K;
    const int* rows; const int* cnt;
    int gshift;
    int varN, varK;
    int act;            // 0 none, 1..4 fixed (act-1), 5 per-expert e&3
    long cStride;       // split-K partial-buffer stride (elements)
    int* zcnt;          // if non-null: block (0,0,0) zeroes 48 counters
    int red;            // split-K epilogue: 1 = atomicAdd into shared C buffer
    const float* abias; // if non-null (rgemm): A = gelu(A[p0]+A[p1]+abias)
    long aStride;       // partial stride for the fused A sum
};

// ---------------- tf32 grouped GEMM (experts), split-K capable ---------------
// BM=32, BN=64; 64 threads = 2 warps; warp tile 32x32; S-stage cp.async.
template<int SPLIT, int S>
__global__ __launch_bounds__(64) void tgemm_k(GArgs g) {
    constexpr int BM  = 32;
    constexpr int BN  = 64;
    constexpr int MI  = 2;
    constexpr int NI  = 4;
    constexpr int BNP = BN + 8;

    const int e  = blockIdx.z;
    const int Me = g.cnt[e];
    if (Me == 0) return;
    const int he = 512 * (2 + (e >> 2));
    const int Ne = g.varN ? he : g.N;
    const int Ke = g.varK ? he : g.K;

    const int ntiles = gridDim.x / SPLIT;
    const int slice  = blockIdx.x / ntiles;
    const int n0     = (blockIdx.x % ntiles) * BN;
    if (n0 >= Ne) return;

    const int Ksl   = Ke / SPLIT;
    const int kbase = slice * Ksl;
    const int KT    = Ksl >> 4;

    float* Cp = g.C + (long)slice * g.cStride;

    const float* Bp = g.B + (long)e * g.bStride;
    const int*   rl = g.rows + e * NPAIR;

    __shared__ float As[S][BM][20];
    __shared__ float Bs[S][16][BNP];

    const int tid = threadIdx.x, lane = tid & 31;
    const int wn = tid >> 5;
    const int grp = lane >> 2, t4 = lane & 3;
    const int a_row = tid >> 1;
    const int aq    = (tid & 1) * 2;

    const int aAct = (g.act == 5) ? (e & 3) : (g.act - 1);

    for (int m0 = blockIdx.y * BM; m0 < Me; m0 += gridDim.y * BM) {
        const bool mv = (m0 + a_row) < Me;
        long arow = 0;
        if (mv) arow = (long)(rl[m0 + a_row] >> g.gshift);
        const float* Ap = g.A + arow * (long)g.lda + kbase;

        int crow[MI * 2];
#pragma unroll
        for (int mi = 0; mi < MI; mi++)
#pragma unroll
            for (int h = 0; h < 2; h++) {
                int m = m0 + mi * 16 + grp + h * 8;
                crow[mi * 2 + h] = (m < Me) ? rl[m] : -1;
            }

        float acc[MI][NI][4];
#pragma unroll
        for (int mi = 0; mi < MI; mi++)
#pragma unroll
            for (int ni = 0; ni < NI; ni++)
#pragma unroll
                for (int c = 0; c < 4; c++) acc[mi][ni][c] = 0.0f;

        auto loadStage = [&](int s, int kt) {
            int k0 = kt << 4;
#pragma unroll
            for (int i = 0; i < 2; i++)
                cpa16(sptr(&As[s][a_row][(aq + i) * 4]), Ap + k0 + (aq + i) * 4, mv);
#pragma unroll
            for (int i = 0; i < 4; i++) {
                int idx = tid + i * 64;
                int r = idx >> 4, col = (idx & 15) * 4;
                cpa16(sptr(&Bs[s][r][col]),
                      Bp + (long)(kbase + k0 + r) * g.ldb + n0 + col, true);
            }
            asm volatile("cp.async.commit_group;");
        };

#pragma unroll
        for (int s = 0; s < S - 1; s++) {
            if (s < KT) loadStage(s, s);
            else        asm volatile("cp.async.commit_group;");
        }

        for (int kt = 0; kt < KT; kt++) {
            asm volatile("cp.async.wait_group %0;" :: "n"(S - 2));
            __syncthreads();
            const int buf = kt % S;

            if (kt + S - 1 < KT) loadStage((kt + S - 1) % S, kt + S - 1);
            else                 asm volatile("cp.async.commit_group;");

#pragma unroll
            for (int ks = 0; ks < 2; ks++) {
                const int kk = ks * 8;
                unsigned a[MI][4], b[NI][2];
#pragma unroll
                for (int mi = 0; mi < MI; mi++) {
                    int mr = mi * 16 + grp;
                    a[mi][0] = f2tf32(As[buf][mr][kk + t4]);
                    a[mi][1] = f2tf32(As[buf][mr + 8][kk + t4]);
                    a[mi][2] = f2tf32(As[buf][mr][kk + t4 + 4]);
                    a[mi][3] = f2tf32(As[buf][mr + 8][kk + t4 + 4]);
                }
#pragma unroll
                for (int ni = 0; ni < NI; ni++) {
                    int nc = wn * 32 + ni * 8 + grp;
                    b[ni][0] = f2tf32(Bs[buf][kk + t4][nc]);
                    b[ni][1] = f2tf32(Bs[buf][kk + t4 + 4][nc]);
                }
#pragma unroll
                for (int mi = 0; mi < MI; mi++)
#pragma unroll
                    for (int ni = 0; ni < NI; ni++)
                        MMA_TF32(acc[mi][ni], a[mi][0], a[mi][1], a[mi][2], a[mi][3],
                                 b[ni][0], b[ni][1]);
            }
        }

#pragma unroll
        for (int ni = 0; ni < NI; ni++) {
            int c = n0 + wn * 32 + ni * 8 + t4 * 2;
            float b0 = 0.0f, b1 = 0.0f;
            if (SPLIT == 1) {
                const float* bias = g.bias + (long)e * g.biasStride;
                b0 = bias[c]; b1 = bias[c + 1];
            }
#pragma unroll
            for (int mi = 0; mi < MI; mi++)
#pragma unroll
                for (int h = 0; h < 2; h++) {
                    int cr = crow[mi * 2 + h];
                    if (cr >= 0) {
                        float v0 = acc[mi][ni][h * 2 + 0] + b0;
                        float v1 = acc[mi][ni][h * 2 + 1] + b1;
                        if (SPLIT == 1 && aAct >= 0) { v0 = actf(aAct, v0); v1 = actf(aAct, v1); }
                        if (SPLIT > 1 && g.red) {
                            atomicAdd(Cp + (long)cr * g.ldc + c,     v0);
                            atomicAdd(Cp + (long)cr * g.ldc + c + 1, v1);
                        } else {
                            *(float2*)(Cp + (long)cr * g.ldc + c) = make_float2(v0, v1);
                        }
                    }
                }
        }
        asm volatile("cp.async.wait_group 0;");
        __syncthreads();
    }
}

// ---------------- router GEMM: split-tf32 (hi/lo), split-K + fused-A sum -----
// If abias != nullptr: A element = gelu(A[off] + A[aStride+off] + abias[col]).
__global__ __launch_bounds__(256) void rgemm_k(GArgs g) {
    const int n0 = blockIdx.x * 64;
    const int m0 = blockIdx.y * 128;
    if (n0 >= g.N) return;
    const int slice = blockIdx.z;

    if (g.zcnt && blockIdx.x == 0 && blockIdx.y == 0 && slice == 0 && threadIdx.x < 48)
        g.zcnt[threadIdx.x] = 0;

    __shared__ unsigned AsH[128][20], AsL[128][20];
    __shared__ unsigned BsH[16][72], BsL[16][72];

    const int tid = threadIdx.x, warp = tid >> 5, lane = tid & 31;
    const int grp = lane >> 2, t4 = lane & 3;
    const int wm = warp >> 1, wn = warp & 1;
    const int a_row = tid >> 1;
    const int aq = (tid & 1) * 2;
    const int bk = tid >> 4, cb = (tid & 15) * 4;

    const bool mv = (m0 + a_row) < g.M;
    const float* Ap = g.A + (long)(m0 + a_row) * g.lda + (long)slice * g.K;
    const float* Bp = g.B + (long)slice * g.K * g.ldb;
    const float* abp = g.abias ? (g.abias + (long)slice * g.K) : nullptr;
    float* Cp = g.C + (long)slice * g.cStride;
    const bool full = (g.cStride == 0);

    float acc[2][4][4];
#pragma unroll
    for (int mi = 0; mi < 2; mi++)
#pragma unroll
        for (int ni = 0; ni < 4; ni++)
#pragma unroll
            for (int c = 0; c < 4; c++) acc[mi][ni][c] = 0.0f;

    float4 av[2], bv;
    auto ldreg = [&](int k0) {
#pragma unroll
        for (int i = 0; i < 2; i++) {
            int off = k0 + (aq + i) * 4;
            if (mv) {
                float4 a0 = *(const float4*)(Ap + off);
                if (abp) {
                    float4 a1 = *(const float4*)(Ap + g.aStride + off);
                    float4 ab = *(const float4*)(abp + off);
                    a0.x = actf(0, a0.x + a1.x + ab.x);
                    a0.y = actf(0, a0.y + a1.y + ab.y);
                    a0.z = actf(0, a0.z + a1.z + ab.z);
                    a0.w = actf(0, a0.w + a1.w + ab.w);
                }
                av[i] = a0;
            } else {
                av[i] = make_float4(0.f, 0.f, 0.f, 0.f);
            }
        }
        bv = *(const float4*)(Bp + (long)(k0 + bk) * g.ldb + n0 + cb);
    };

    const int KT = g.K >> 4;
    ldreg(0);
    for (int kt = 0; kt < KT; kt++) {
        __syncthreads();
#pragma unroll
        for (int i = 0; i < 2; i++) {
            float vv[4] = {av[i].x, av[i].y, av[i].z, av[i].w};
            uint4 uh, ul;
            unsigned* ph = &uh.x; unsigned* pl = &ul.x;
#pragma unroll
            for (int c = 0; c < 4; c++) {
                unsigned hb = f2tf32(vv[c]);
                ph[c] = hb;
                pl[c] = f2tf32(vv[c] - __uint_as_float(hb));
            }
            *(uint4*)&AsH[a_row][(aq + i) * 4] = uh;
            *(uint4*)&AsL[a_row][(aq + i) * 4] = ul;
        }
        {
            float vv[4] = {bv.x, bv.y, bv.z, bv.w};
            uint4 uh, ul;
            unsigned* ph = &uh.x; unsigned* pl = &ul.x;
#pragma unroll
            for (int c = 0; c < 4; c++) {
                unsigned hb = f2tf32(vv[c]);
                ph[c] = hb;
                pl[c] = f2tf32(vv[c] - __uint_as_float(hb));
            }
            *(uint4*)&BsH[bk][cb] = uh;
            *(uint4*)&BsL[bk][cb] = ul;
        }
        __syncthreads();

        if (kt + 1 < KT) ldreg((kt + 1) << 4);

#pragma unroll
        for (int ks = 0; ks < 2; ks++) {
            const int kk = ks * 8;
            unsigned ah[2][4], al[2][4], bh[4][2], bl[4][2];
#pragma unroll
            for (int mi = 0; mi < 2; mi++) {
                int mr = wm * 32 + mi * 16 + grp;
                ah[mi][0] = AsH[mr][kk + t4];     al[mi][0] = AsL[mr][kk + t4];
                ah[mi][1] = AsH[mr + 8][kk + t4]; al[mi][1] = AsL[mr + 8][kk + t4];
                ah[mi][2] = AsH[mr][kk + t4 + 4]; al[mi][2] = AsL[mr][kk + t4 + 4];
                ah[mi][3] = AsH[mr + 8][kk + t4 + 4]; al[mi][3] = AsL[mr + 8][kk + t4 + 4];
            }
#pragma unroll
            for (int ni = 0; ni < 4; ni++) {
                int nc = wn * 32 + ni * 8 + grp;
                bh[ni][0] = BsH[kk + t4][nc];     bl[ni][0] = BsL[kk + t4][nc];
                bh[ni][1] = BsH[kk + t4 + 4][nc]; bl[ni][1] = BsL[kk + t4 + 4][nc];
            }
#pragma unroll
            for (int mi = 0; mi < 2; mi++)
#pragma unroll
                for (int ni = 0; ni < 4; ni++) {
                    MMA_TF32(acc[mi][ni], ah[mi][0], ah[mi][1], ah[mi][2], ah[mi][3],
                             bh[ni][0], bh[ni][1]);
                    MMA_TF32(acc[mi][ni], ah[mi][0], ah[mi][1], ah[mi][2], ah[mi][3],
                             bl[ni][0], bl[ni][1]);
                    MMA_TF32(acc[mi][ni], al[mi][0], al[mi][1], al[mi][2], al[mi][3],
                             bh[ni][0], bh[ni][1]);
                }
        }
    }

    const int aAct = g.act - 1;
#pragma unroll
    for (int ni = 0; ni < 4; ni++) {
        int c = n0 + wn * 32 + ni * 8 + t4 * 2;
        float b0 = 0.0f, b1 = 0.0f;
        if (full) { b0 = g.bias[c]; b1 = g.bias[c + 1]; }
#pragma unroll
        for (int mi = 0; mi < 2; mi++)
#pragma unroll
            for (int h = 0; h < 2; h++) {
                int m = m0 + wm * 32 + mi * 16 + grp + h * 8;
                if (m < g.M) {
                    float v0 = acc[mi][ni][h * 2 + 0] + b0;
                    float v1 = acc[mi][ni][h * 2 + 1] + b1;
                    if (full && aAct >= 0) { v0 = actf(aAct, v0); v1 = actf(aAct, v1); }
                    *(float2*)(Cp + (long)m * g.ldc + c) = make_float2(v0, v1);
                }
            }
    }
}

// ---------------- softmax + top-k + routing (register-resident, 2 syncs) -----
__global__ __launch_bounds__(256) void route_k(const float* scores, const float* sbias,
                                               const float* temp,
                                               float* w, int* prei, int* mlpi, int* posti,
                                               int* cnt, int* rows) {
    const int t = blockIdx.x, tid = threadIdx.x;
    const int wid = tid >> 5, lane = tid & 31;
    __shared__ float ws1[8], ws2[8];
    __shared__ float cval[64];
    __shared__ int   cidx[64];

    const float invT = 1.0f / temp[0];
    const long TN = (long)T * NSCORE;

    float v[16];
    const int baseIdx = wid * 512 + lane;
#pragma unroll
    for (int j = 0; j < 16; j++) {
        int idx = baseIdx + 32 * j;
        long off = (long)t * NSCORE + idx;
        v[j] = (scores[off] + scores[TN + off] + sbias[idx]) * invT;
    }

    float mx = v[0];
#pragma unroll
    for (int j = 1; j < 16; j++) mx = fmaxf(mx, v[j]);
    mx = wmax(mx);
    if (lane == 0) ws1[wid] = mx;
    __syncthreads();
    float gmax = ws1[0];
#pragma unroll
    for (int i = 1; i < 8; i++) gmax = fmaxf(gmax, ws1[i]);

    float sum = 0.0f;
#pragma unroll
    for (int j = 0; j < 16; j++) sum += expf(v[j] - gmax);
    sum = wsum(sum);
    if (lane == 0) ws2[wid] = sum;

#pragma unroll
    for (int k = 0; k < TOPK; k++) {
        float bv = -3.4e38f; int bi = NSCORE;
#pragma unroll
        for (int j = 0; j < 16; j++) {
            if (v[j] > bv) { bv = v[j]; bi = baseIdx + 32 * j; }
        }
#pragma unroll
        for (int o = 16; o; o >>= 1) {
            float ov = __shfl_xor_sync(0xffffffffu, bv, o);
            int   oi = __shfl_xor_sync(0xffffffffu, bi, o);
            if (ov > bv || (ov == bv && oi < bi)) { bv = ov; bi = oi; }
        }
        if (lane == 0) { cval[wid * 8 + k] = bv; cidx[wid * 8 + k] = bi; }
        if ((bi & 31) == lane) v[(bi >> 5) & 15] = -3.4e38f;
    }
    __syncthreads();

    float gsum = ws2[0];
#pragma unroll
    for (int i = 1; i < 8; i++) gsum += ws2[i];

    if (wid == 0) {
        float cv0 = cval[lane], cv1 = cval[lane + 32];
        int   ci0 = cidx[lane], ci1 = cidx[lane + 32];
        float myv = 0.0f; int myi = 0;
#pragma unroll
        for (int k = 0; k < TOPK; k++) {
            float bv; int bi;
            if (cv0 > cv1 || (cv0 == cv1 && ci0 < ci1)) { bv = cv0; bi = ci0; }
            else                                        { bv = cv1; bi = ci1; }
#pragma unroll
            for (int o = 16; o; o >>= 1) {
                float ov = __shfl_xor_sync(0xffffffffu, bv, o);
                int   oi = __shfl_xor_sync(0xffffffffu, bi, o);
                if (ov > bv || (ov == bv && oi < bi)) { bv = ov; bi = oi; }
            }
            if (lane == k) { myv = bv; myi = bi; }
            if (ci0 == bi) cv0 = -3.4e38f;
            if (ci1 == bi) cv1 = -3.4e38f;
        }
        if (lane < TOPK) {
            float prob = expf(myv - gmax) / gsum;
            float ww = (prob >= 1e-6f) ? prob : 0.0f;
            int pair = t * TOPK + lane;
            int pe = myi >> 8, rem = myi & 255, me = rem >> 4, oe = rem & 15;
            prei[pair] = pe; mlpi[pair] = me; posti[pair] = oe; w[pair] = ww;
            int s0 = atomicAdd(&cnt[pe], 1);       rows[pe * NPAIR + s0] = pair;
            int s1 = atomicAdd(&cnt[16 + me], 1);  rows[(16 + me) * NPAIR + s1] = pair;
            int s2 = atomicAdd(&cnt[32 + oe], 1);  rows[(32 + oe) * NPAIR + s2] = pair;
        }
    }
}

// ---------------- pre: sum 2 partials + bias + LN + act; also init y=bias ----
__global__ __launch_bounds__(256) void prelnact_k(const float* U, const int* prei,
                                                  const float* pbias,
                                                  const float* g, const float* b, float* X,
                                                  const int* mlpi, const float* mb2, float* y) {
    const int warp = threadIdx.x >> 5, lane = threadIdx.x & 31;
    const int p = blockIdx.x * 8 + warp;
    const int e = prei[p];
    const int e2 = mlpi[p];
    float u[16];
#pragma unroll
    for (int j = 0; j < 16; j++) {
        int idx = lane + 32 * j;
        u[j] = U[p * D + idx] + U[(long)NPAIR * D + p * D + idx] + pbias[e * D + idx];
        y[(long)p * D + idx] = mb2[e2 * D + idx];   // bias-init for mlp2 atomic acc
    }

    float s = 0.0f;
#pragma unroll
    for (int j = 0; j < 16; j++) s += u[j];
    const float mean = wsum(s) * (1.0f / D);

    float v = 0.0f;
#pragma unroll
    for (int j = 0; j < 16; j++) { float d = u[j] - mean; v += d * d; }
    const float rstd = rsqrtf(wsum(v) * (1.0f / D) + 1e-5f);

    const int a = e & 3;
#pragma unroll
    for (int j = 0; j < 16; j++) {
        int idx = lane + 32 * j;
        float val = (u[j] - mean) * rstd * g[e * D + idx] + b[e * D + idx];
        X[p * D + idx] = actf(a, val);
    }
}

// ---------------- post: sum 2 partials + bias + LN + weighted reduce ---------
__global__ __launch_bounds__(256) void final_k(const float* Z, const int* posti, const float* w,
                                               const float* pbias,
                                               const float* g, const float* b, float* out) {
    const int t = blockIdx.x, tid = threadIdx.x;
    const int warp = tid >> 5, lane = tid & 31;
    __shared__ float sacc[8][D];

    const int pair = t * TOPK + warp;
    const int e = posti[pair];
    const float ww = w[pair];
    float z[16];
#pragma unroll
    for (int j = 0; j < 16; j++) {
        int idx = lane + 32 * j;
        z[j] = Z[(long)pair * D + idx] + Z[(long)NPAIR * D + (long)pair * D + idx]
             + pbias[e * D + idx];
    }

    if ((e & 1) == 0) {
        float s = 0.0f;
#pragma unroll
        for (int j = 0; j < 16; j++) s += z[j];
        const float mean = wsum(s) * (1.0f / D);
        float v = 0.0f;
#pragma unroll
        for (int j = 0; j < 16; j++) { float d = z[j] - mean; v += d * d; }
        const float rstd = rsqrtf(wsum(v) * (1.0f / D) + 1e-5f);
#pragma unroll
        for (int j = 0; j < 16; j++) {
            int idx = lane + 32 * j;
            z[j] = (z[j] - mean) * rstd * g[e * D + idx] + b[e * D + idx];
        }
    }
#pragma unroll
    for (int j = 0; j < 16; j++) sacc[warp][lane + 32 * j] = ww * z[j];
    __syncthreads();

    for (int i = tid; i < D; i += 256) {
        float s = 0.0f;
#pragma unroll
        for (int k = 0; k < 8; k++) s += sacc[k][i];
        out[t * D + i] = s;
    }
}

// ---------------- launch -----------------------------------------------------
extern "C" void kernel_launch(void* const* d_in, const int* in_sizes, int n_in,
                              void* d_out, int out_size) {
    const float* x       = (const float*)d_in[0];
    const float* r_w1    = (const float*)d_in[1];
    const float* r_b1    = (const float*)d_in[2];
    const float* r_w2    = (const float*)d_in[3];
    const float* r_b2    = (const float*)d_in[4];
    const float* r_w3    = (const float*)d_in[5];
    const float* r_b3    = (const float*)d_in[6];
    const float* temp    = (const float*)d_in[7];
    const float* pre_w   = (const float*)d_in[8];
    const float* pre_b   = (const float*)d_in[9];
    const float* pre_g   = (const float*)d_in[10];
    const float* pre_be  = (const float*)d_in[11];
    const float* mlp_w1  = (const float*)d_in[12];
    const float* mlp_b1  = (const float*)d_in[13];
    const float* mlp_w2  = (const float*)d_in[14];
    const float* mlp_b2  = (const float*)d_in[15];
    const float* post_w  = (const float*)d_in[16];
    const float* post_b  = (const float*)d_in[17];
    const float* post_g  = (const float*)d_in[18];
    const float* post_be = (const float*)d_in[19];
    float* out = (float*)d_out;

    float *h1, *h2, *sc, *preu, *xin, *hmid, *y, *z, *w;
    int *prei, *mlpi, *posti, *cnt, *rows;
    cudaGetSymbolAddress((void**)&h1, g_h1);
    cudaGetSymbolAddress((void**)&h2, g_h2);
    cudaGetSymbolAddress((void**)&sc, g_scores);
    cudaGetSymbolAddress((void**)&preu, g_preu);
    cudaGetSymbolAddress((void**)&xin, g_xin);
    cudaGetSymbolAddress((void**)&hmid, g_hmid);
    cudaGetSymbolAddress((void**)&y, g_y);
    cudaGetSymbolAddress((void**)&z, g_z);
    cudaGetSymbolAddress((void**)&w, g_w);
    cudaGetSymbolAddress((void**)&prei, g_prei);
    cudaGetSymbolAddress((void**)&mlpi, g_mlpi);
    cudaGetSymbolAddress((void**)&posti, g_posti);
    cudaGetSymbolAddress((void**)&cnt, g_cnt);
    cudaGetSymbolAddress((void**)&rows, g_rows);

    // fc1: split-K=2 (z), partials -> h1[2]; block 0 zeroes routing counters
    {
        GArgs a = {x, D, r_w1, 0, 512, r_b1, 0, h1, 512,
                   T, 512, 256, nullptr, nullptr, 0, 0, 0, 1,
                   (long)T * 512, cnt, 0, nullptr, 0};
        rgemm_k<<<dim3(8, 2, 2), 256>>>(a);
    }
    // fc2: A = gelu(h1p0 + h1p1 + r_b1); split-K=2 -> h2[2]
    {
        GArgs a = {h1, 512, r_w2, 0, 256, r_b2, 0, h2, 256,
                   T, 256, 256, nullptr, nullptr, 0, 0, 0, 1,
                   (long)T * 256, nullptr, 0, r_b1, (long)T * 512};
        rgemm_k<<<dim3(4, 2, 2), 256>>>(a);
    }
    // fc3: A = gelu(h2p0 + h2p1 + r_b2); split-K=2 -> score partials
    {
        GArgs a = {h2, 256, r_w3, 0, NSCORE, r_b3, 0, sc, NSCORE,
                   T, NSCORE, 128, nullptr, nullptr, 0, 0, 0, 0,
                   (long)T * NSCORE, nullptr, 0, r_b2, (long)T * 256};
        rgemm_k<<<dim3(64, 2, 2), 256>>>(a);
    }

    route_k<<<T, 256>>>(sc, r_b3, temp, w, prei, mlpi, posti, cnt, rows);

    // pre: split-K=2, S=4
    {
        GArgs a = {x, D, pre_w, (long)D * D, D, pre_b, D, preu, D,
                   NPAIR, D, D, rows, cnt, 3, 0, 0, 0, (long)NPAIR * D,
                   nullptr, 0, nullptr, 0};
        tgemm_k<2, 4><<<dim3(16, 6, NEXP), 64>>>(a);
    }
    // pre LN + act; also initializes y = mlp_b2[mlpi] for mlp2 accumulation
    prelnact_k<<<NPAIR / 8, 256>>>(preu, prei, pre_b, pre_g, pre_be, xin,
                                   mlpi, mlp_b2, y);

    // mlp1: fused bias+act, S=3
    {
        GArgs a = {xin, D, mlp_w1, (long)D * MAXH, MAXH, mlp_b1, MAXH, hmid, MAXH,
                   NPAIR, MAXH, D, rows + 16 * NPAIR, cnt + 16, 0, 1, 0, 5, 0,
                   nullptr, 0, nullptr, 0};
        tgemm_k<1, 3><<<dim3(40, 6, NEXP), 64>>>(a);
    }
    // mlp2: split-K=4, S=3, slices atomically accumulate into bias-initialized y
    {
        GArgs a = {hmid, MAXH, mlp_w2, (long)MAXH * D, D, mlp_b2, D, y, D,
                   NPAIR, D, MAXH, rows + 16 * NPAIR, cnt + 16, 0, 0, 1, 0,
                   0, nullptr, 1, nullptr, 0};
        tgemm_k<4, 3><<<dim3(32, 6, NEXP), 64>>>(a);
    }

    // post: split-K=2, S=4
    {
        GArgs a = {y, D, post_w, (long)D * D, D, post_b, D, z, D,
                   NPAIR, D, D, rows + 32 * NPAIR, cnt + 32, 0, 0, 0, 0,
                   (long)NPAIR * D, nullptr, 0, nullptr, 0};
        tgemm_k<2, 4><<<dim3(16, 6, NEXP), 64>>>(a);
    }

    final_k<<<T, 256>>>(z, posti, w, post_b, post_g, post_be, out);
}

// round 17
// speedup vs baseline: 1.1260x; 1.0058x over previous
#include <cuda_runtime.h>
#include <math.h>
#include <stdint.h>

#define D      512
#define T      256
#define TOPK   8
#define NPAIR  2048
#define NEXP   16
#define MAXH   2560
#define NSCORE 4096

// ---------------- scratch ----------------------------------------------------
__device__ float g_h1[2 * T * D];            // 2 split-K partials (fc1)
__device__ float g_h2[2 * T * 256];          // 2 split-K partials (fc2)
__device__ float g_scores[2 * T * NSCORE];   // 2 split-K partials (fc3)
__device__ float g_preu[2 * NPAIR * D];      // 2 split-K partials
__device__ float g_xin[NPAIR * D];
__device__ float g_hmid[NPAIR * MAXH];
__device__ float g_y[NPAIR * D];             // mlp2 output (bias-init + atomic acc)
__device__ float g_z[2 * NPAIR * D];         // 2 split-K partials (post)
__device__ float g_w[NPAIR];
__device__ int   g_prei[NPAIR];
__device__ int   g_mlpi[NPAIR];
__device__ int   g_posti[NPAIR];
__device__ int   g_cnt[48];
__device__ int   g_rows[48 * NPAIR];

// ---------------- helpers ----------------------------------------------------
__device__ __forceinline__ float actf(int a, float v) {
    switch (a) {
        case 0: return 0.5f * v * (1.0f + erff(v * 0.7071067811865476f));
        case 1: return fmaxf(v, 0.0f);
        case 2: return tanhf(v);
        default: return v / (1.0f + expf(-v));
    }
}

__device__ __forceinline__ unsigned f2tf32(float f) {
    unsigned r;
    asm("cvt.rna.tf32.f32 %0, %1;" : "=r"(r) : "f"(f));
    return r;
}

__device__ __forceinline__ uint32_t sptr(const void* p) {
    return (uint32_t)__cvta_generic_to_shared(p);
}

__device__ __forceinline__ void cpa16(uint32_t d, const float* s, bool pred) {
    int sz = pred ? 16 : 0;
    asm volatile("cp.async.cg.shared.global [%0], [%1], 16, %2;"
                 :: "r"(d), "l"(s), "r"(sz));
}

__device__ __forceinline__ float wsum(float v) {
#pragma unroll
    for (int o = 16; o; o >>= 1) v += __shfl_xor_sync(0xffffffffu, v, o);
    return v;
}
__device__ __forceinline__ float wmax(float v) {
#pragma unroll
    for (int o = 16; o; o >>= 1) v = fmaxf(v, __shfl_xor_sync(0xffffffffu, v, o));
    return v;
}

#define MMA_TF32(c, a0, a1, a2, a3, b0, b1)                                      \
    asm volatile("mma.sync.aligned.m16n8k8.row.col.f32.tf32.tf32.f32 "           \
                 "{%0,%1,%2,%3}, {%4,%5,%6,%7}, {%8,%9}, {%0,%1,%2,%3};"         \
                 : "+f"((c)[0]), "+f"((c)[1]), "+f"((c)[2]), "+f"((c)[3])        \
                 : "r"(a0), "r"(a1), "r"(a2), "r"(a3), "r"(b0), "r"(b1))

struct GArgs {
    const float* A; int lda;
    const float* B; long bStride; int ldb;
    const float* bias; int biasStride;
    float* C; int ldc;
    int M, N, K;
    const int* rows; const int* cnt;
    int gshift;
    int varN, varK;
    int act;            // 0 none, 1..4 fixed (act-1), 5 per-expert e&3
    long cStride;       // split-K partial-buffer stride (elements)
    int* zcnt;          // if non-null: block (0,0,0) zeroes 48 counters
    int red;            // split-K epilogue: 1 = atomicAdd into shared C buffer
    const float* abias; // if non-null (rgemm): A = gelu(A[p0]+A[p1]+abias)
    long aStride;       // partial stride for the fused A sum
};

// ---------------- tf32 grouped GEMM (experts), split-K capable ---------------
// NW warps (2 or 4): BM=16*NW, BN=64, warp tile 32x32 (MI=2, NI=4).
// S-stage cp.async pipeline.
template<int SPLIT, int S, int NW>
__global__ __launch_bounds__(32 * NW) void tgemm_k(GArgs g) {
    constexpr int BM  = 16 * NW;
    constexpr int BN  = 64;
    constexpr int MI  = 2;
    constexpr int NI  = 4;
    constexpr int BNP = BN + 8;
    constexpr int NT  = 32 * NW;
    constexpr int BL  = 8 / NW;          // B float4 loads per thread

    const int e  = blockIdx.z;
    const int Me = g.cnt[e];
    if (Me == 0) return;
    const int he = 512 * (2 + (e >> 2));
    const int Ne = g.varN ? he : g.N;
    const int Ke = g.varK ? he : g.K;

    const int ntiles = gridDim.x / SPLIT;
    const int slice  = blockIdx.x / ntiles;
    const int n0     = (blockIdx.x % ntiles) * BN;
    if (n0 >= Ne) return;

    const int Ksl   = Ke / SPLIT;
    const int kbase = slice * Ksl;
    const int KT    = Ksl >> 4;

    float* Cp = g.C + (long)slice * g.cStride;

    const float* Bp = g.B + (long)e * g.bStride;
    const int*   rl = g.rows + e * NPAIR;

    __shared__ float As[S][BM][20];
    __shared__ float Bs[S][16][BNP];

    const int tid = threadIdx.x, lane = tid & 31;
    const int warp = tid >> 5;
    const int wn = warp & 1, wm = warp >> 1;
    const int grp = lane >> 2, t4 = lane & 3;
    const int a_row = tid >> 1;
    const int aq    = (tid & 1) * 2;

    const int aAct = (g.act == 5) ? (e & 3) : (g.act - 1);

    for (int m0 = blockIdx.y * BM; m0 < Me; m0 += gridDim.y * BM) {
        const bool mv = (m0 + a_row) < Me;
        long arow = 0;
        if (mv) arow = (long)(rl[m0 + a_row] >> g.gshift);
        const float* Ap = g.A + arow * (long)g.lda + kbase;

        int crow[MI * 2];
#pragma unroll
        for (int mi = 0; mi < MI; mi++)
#pragma unroll
            for (int h = 0; h < 2; h++) {
                int m = m0 + wm * 32 + mi * 16 + grp + h * 8;
                crow[mi * 2 + h] = (m < Me) ? rl[m] : -1;
            }

        float acc[MI][NI][4];
#pragma unroll
        for (int mi = 0; mi < MI; mi++)
#pragma unroll
            for (int ni = 0; ni < NI; ni++)
#pragma unroll
                for (int c = 0; c < 4; c++) acc[mi][ni][c] = 0.0f;

        auto loadStage = [&](int s, int kt) {
            int k0 = kt << 4;
#pragma unroll
            for (int i = 0; i < 2; i++)
                cpa16(sptr(&As[s][a_row][(aq + i) * 4]), Ap + k0 + (aq + i) * 4, mv);
#pragma unroll
            for (int i = 0; i < BL; i++) {
                int idx = tid + i * NT;
                int r = idx >> 4, col = (idx & 15) * 4;
                cpa16(sptr(&Bs[s][r][col]),
                      Bp + (long)(kbase + k0 + r) * g.ldb + n0 + col, true);
            }
            asm volatile("cp.async.commit_group;");
        };

#pragma unroll
        for (int s = 0; s < S - 1; s++) {
            if (s < KT) loadStage(s, s);
            else        asm volatile("cp.async.commit_group;");
        }

        for (int kt = 0; kt < KT; kt++) {
            asm volatile("cp.async.wait_group %0;" :: "n"(S - 2));
            __syncthreads();
            const int buf = kt % S;

            if (kt + S - 1 < KT) loadStage((kt + S - 1) % S, kt + S - 1);
            else                 asm volatile("cp.async.commit_group;");

#pragma unroll
            for (int ks = 0; ks < 2; ks++) {
                const int kk = ks * 8;
                unsigned a[MI][4], b[NI][2];
#pragma unroll
                for (int mi = 0; mi < MI; mi++) {
                    int mr = wm * 32 + mi * 16 + grp;
                    a[mi][0] = f2tf32(As[buf][mr][kk + t4]);
                    a[mi][1] = f2tf32(As[buf][mr + 8][kk + t4]);
                    a[mi][2] = f2tf32(As[buf][mr][kk + t4 + 4]);
                    a[mi][3] = f2tf32(As[buf][mr + 8][kk + t4 + 4]);
                }
#pragma unroll
                for (int ni = 0; ni < NI; ni++) {
                    int nc = wn * 32 + ni * 8 + grp;
                    b[ni][0] = f2tf32(Bs[buf][kk + t4][nc]);
                    b[ni][1] = f2tf32(Bs[buf][kk + t4 + 4][nc]);
                }
#pragma unroll
                for (int mi = 0; mi < MI; mi++)
#pragma unroll
                    for (int ni = 0; ni < NI; ni++)
                        MMA_TF32(acc[mi][ni], a[mi][0], a[mi][1], a[mi][2], a[mi][3],
                                 b[ni][0], b[ni][1]);
            }
        }

#pragma unroll
        for (int ni = 0; ni < NI; ni++) {
            int c = n0 + wn * 32 + ni * 8 + t4 * 2;
            float b0 = 0.0f, b1 = 0.0f;
            if (SPLIT == 1) {
                const float* bias = g.bias + (long)e * g.biasStride;
                b0 = bias[c]; b1 = bias[c + 1];
            }
#pragma unroll
            for (int mi = 0; mi < MI; mi++)
#pragma unroll
                for (int h = 0; h < 2; h++) {
                    int cr = crow[mi * 2 + h];
                    if (cr >= 0) {
                        float v0 = acc[mi][ni][h * 2 + 0] + b0;
                        float v1 = acc[mi][ni][h * 2 + 1] + b1;
                        if (SPLIT == 1 && aAct >= 0) { v0 = actf(aAct, v0); v1 = actf(aAct, v1); }
                        if (SPLIT > 1 && g.red) {
                            atomicAdd(Cp + (long)cr * g.ldc + c,     v0);
                            atomicAdd(Cp + (long)cr * g.ldc + c + 1, v1);
                        } else {
                            *(float2*)(Cp + (long)cr * g.ldc + c) = make_float2(v0, v1);
                        }
                    }
                }
        }
        asm volatile("cp.async.wait_group 0;");
        __syncthreads();
    }
}

// ---------------- router GEMM: split-tf32 (hi/lo), split-K + fused-A sum -----
__global__ __launch_bounds__(256) void rgemm_k(GArgs g) {
    const int n0 = blockIdx.x * 64;
    const int m0 = blockIdx.y * 128;
    if (n0 >= g.N) return;
    const int slice = blockIdx.z;

    if (g.zcnt && blockIdx.x == 0 && blockIdx.y == 0 && slice == 0 && threadIdx.x < 48)
        g.zcnt[threadIdx.x] = 0;

    __shared__ unsigned AsH[128][20], AsL[128][20];
    __shared__ unsigned BsH[16][72], BsL[16][72];

    const int tid = threadIdx.x, warp = tid >> 5, lane = tid & 31;
    const int grp = lane >> 2, t4 = lane & 3;
    const int wm = warp >> 1, wn = warp & 1;
    const int a_row = tid >> 1;
    const int aq = (tid & 1) * 2;
    const int bk = tid >> 4, cb = (tid & 15) * 4;

    const bool mv = (m0 + a_row) < g.M;
    const float* Ap = g.A + (long)(m0 + a_row) * g.lda + (long)slice * g.K;
    const float* Bp = g.B + (long)slice * g.K * g.ldb;
    const float* abp = g.abias ? (g.abias + (long)slice * g.K) : nullptr;
    float* Cp = g.C + (long)slice * g.cStride;
    const bool full = (g.cStride == 0);

    float acc[2][4][4];
#pragma unroll
    for (int mi = 0; mi < 2; mi++)
#pragma unroll
        for (int ni = 0; ni < 4; ni++)
#pragma unroll
            for (int c = 0; c < 4; c++) acc[mi][ni][c] = 0.0f;

    float4 av[2], bv;
    auto ldreg = [&](int k0) {
#pragma unroll
        for (int i = 0; i < 2; i++) {
            int off = k0 + (aq + i) * 4;
            if (mv) {
                float4 a0 = *(const float4*)(Ap + off);
                if (abp) {
                    float4 a1 = *(const float4*)(Ap + g.aStride + off);
                    float4 ab = *(const float4*)(abp + off);
                    a0.x = actf(0, a0.x + a1.x + ab.x);
                    a0.y = actf(0, a0.y + a1.y + ab.y);
                    a0.z = actf(0, a0.z + a1.z + ab.z);
                    a0.w = actf(0, a0.w + a1.w + ab.w);
                }
                av[i] = a0;
            } else {
                av[i] = make_float4(0.f, 0.f, 0.f, 0.f);
            }
        }
        bv = *(const float4*)(Bp + (long)(k0 + bk) * g.ldb + n0 + cb);
    };

    const int KT = g.K >> 4;
    ldreg(0);
    for (int kt = 0; kt < KT; kt++) {
        __syncthreads();
#pragma unroll
        for (int i = 0; i < 2; i++) {
            float vv[4] = {av[i].x, av[i].y, av[i].z, av[i].w};
            uint4 uh, ul;
            unsigned* ph = &uh.x; unsigned* pl = &ul.x;
#pragma unroll
            for (int c = 0; c < 4; c++) {
                unsigned hb = f2tf32(vv[c]);
                ph[c] = hb;
                pl[c] = f2tf32(vv[c] - __uint_as_float(hb));
            }
            *(uint4*)&AsH[a_row][(aq + i) * 4] = uh;
            *(uint4*)&AsL[a_row][(aq + i) * 4] = ul;
        }
        {
            float vv[4] = {bv.x, bv.y, bv.z, bv.w};
            uint4 uh, ul;
            unsigned* ph = &uh.x; unsigned* pl = &ul.x;
#pragma unroll
            for (int c = 0; c < 4; c++) {
                unsigned hb = f2tf32(vv[c]);
                ph[c] = hb;
                pl[c] = f2tf32(vv[c] - __uint_as_float(hb));
            }
            *(uint4*)&BsH[bk][cb] = uh;
            *(uint4*)&BsL[bk][cb] = ul;
        }
        __syncthreads();

        if (kt + 1 < KT) ldreg((kt + 1) << 4);

#pragma unroll
        for (int ks = 0; ks < 2; ks++) {
            const int kk = ks * 8;
            unsigned ah[2][4], al[2][4], bh[4][2], bl[4][2];
#pragma unroll
            for (int mi = 0; mi < 2; mi++) {
                int mr = wm * 32 + mi * 16 + grp;
                ah[mi][0] = AsH[mr][kk + t4];     al[mi][0] = AsL[mr][kk + t4];
                ah[mi][1] = AsH[mr + 8][kk + t4]; al[mi][1] = AsL[mr + 8][kk + t4];
                ah[mi][2] = AsH[mr][kk + t4 + 4]; al[mi][2] = AsL[mr][kk + t4 + 4];
                ah[mi][3] = AsH[mr + 8][kk + t4 + 4]; al[mi][3] = AsL[mr + 8][kk + t4 + 4];
            }
#pragma unroll
            for (int ni = 0; ni < 4; ni++) {
                int nc = wn * 32 + ni * 8 + grp;
                bh[ni][0] = BsH[kk + t4][nc];     bl[ni][0] = BsL[kk + t4][nc];
                bh[ni][1] = BsH[kk + t4 + 4][nc]; bl[ni][1] = BsL[kk + t4 + 4][nc];
            }
#pragma unroll
            for (int mi = 0; mi < 2; mi++)
#pragma unroll
                for (int ni = 0; ni < 4; ni++) {
                    MMA_TF32(acc[mi][ni], ah[mi][0], ah[mi][1], ah[mi][2], ah[mi][3],
                             bh[ni][0], bh[ni][1]);
                    MMA_TF32(acc[mi][ni], ah[mi][0], ah[mi][1], ah[mi][2], ah[mi][3],
                             bl[ni][0], bl[ni][1]);
                    MMA_TF32(acc[mi][ni], al[mi][0], al[mi][1], al[mi][2], al[mi][3],
                             bh[ni][0], bh[ni][1]);
                }
        }
    }

    const int aAct = g.act - 1;
#pragma unroll
    for (int ni = 0; ni < 4; ni++) {
        int c = n0 + wn * 32 + ni * 8 + t4 * 2;
        float b0 = 0.0f, b1 = 0.0f;
        if (full) { b0 = g.bias[c]; b1 = g.bias[c + 1]; }
#pragma unroll
        for (int mi = 0; mi < 2; mi++)
#pragma unroll
            for (int h = 0; h < 2; h++) {
                int m = m0 + wm * 32 + mi * 16 + grp + h * 8;
                if (m < g.M) {
                    float v0 = acc[mi][ni][h * 2 + 0] + b0;
                    float v1 = acc[mi][ni][h * 2 + 1] + b1;
                    if (full && aAct >= 0) { v0 = actf(aAct, v0); v1 = actf(aAct, v1); }
                    *(float2*)(Cp + (long)m * g.ldc + c) = make_float2(v0, v1);
                }
            }
    }
}

// ---------------- softmax + top-k + routing (register-resident, 2 syncs) -----
__global__ __launch_bounds__(256) void route_k(const float* scores, const float* sbias,
                                               const float* temp,
                                               float* w, int* prei, int* mlpi, int* posti,
                                               int* cnt, int* rows) {
    const int t = blockIdx.x, tid = threadIdx.x;
    const int wid = tid >> 5, lane = tid & 31;
    __shared__ float ws1[8], ws2[8];
    __shared__ float cval[64];
    __shared__ int   cidx[64];

    const float invT = 1.0f / temp[0];
    const long TN = (long)T * NSCORE;

    float v[16];
    const int baseIdx = wid * 512 + lane;
#pragma unroll
    for (int j = 0; j < 16; j++) {
        int idx = baseIdx + 32 * j;
        long off = (long)t * NSCORE + idx;
        v[j] = (scores[off] + scores[TN + off] + sbias[idx]) * invT;
    }

    float mx = v[0];
#pragma unroll
    for (int j = 1; j < 16; j++) mx = fmaxf(mx, v[j]);
    mx = wmax(mx);
    if (lane == 0) ws1[wid] = mx;
    __syncthreads();
    float gmax = ws1[0];
#pragma unroll
    for (int i = 1; i < 8; i++) gmax = fmaxf(gmax, ws1[i]);

    float sum = 0.0f;
#pragma unroll
    for (int j = 0; j < 16; j++) sum += expf(v[j] - gmax);
    sum = wsum(sum);
    if (lane == 0) ws2[wid] = sum;

#pragma unroll
    for (int k = 0; k < TOPK; k++) {
        float bv = -3.4e38f; int bi = NSCORE;
#pragma unroll
        for (int j = 0; j < 16; j++) {
            if (v[j] > bv) { bv = v[j]; bi = baseIdx + 32 * j; }
        }
#pragma unroll
        for (int o = 16; o; o >>= 1) {
            float ov = __shfl_xor_sync(0xffffffffu, bv, o);
            int   oi = __shfl_xor_sync(0xffffffffu, bi, o);
            if (ov > bv || (ov == bv && oi < bi)) { bv = ov; bi = oi; }
        }
        if (lane == 0) { cval[wid * 8 + k] = bv; cidx[wid * 8 + k] = bi; }
        if ((bi & 31) == lane) v[(bi >> 5) & 15] = -3.4e38f;
    }
    __syncthreads();

    float gsum = ws2[0];
#pragma unroll
    for (int i = 1; i < 8; i++) gsum += ws2[i];

    if (wid == 0) {
        float cv0 = cval[lane], cv1 = cval[lane + 32];
        int   ci0 = cidx[lane], ci1 = cidx[lane + 32];
        float myv = 0.0f; int myi = 0;
#pragma unroll
        for (int k = 0; k < TOPK; k++) {
            float bv; int bi;
            if (cv0 > cv1 || (cv0 == cv1 && ci0 < ci1)) { bv = cv0; bi = ci0; }
            else                                        { bv = cv1; bi = ci1; }
#pragma unroll
            for (int o = 16; o; o >>= 1) {
                float ov = __shfl_xor_sync(0xffffffffu, bv, o);
                int   oi = __shfl_xor_sync(0xffffffffu, bi, o);
                if (ov > bv || (ov == bv && oi < bi)) { bv = ov; bi = oi; }
            }
            if (lane == k) { myv = bv; myi = bi; }
            if (ci0 == bi) cv0 = -3.4e38f;
            if (ci1 == bi) cv1 = -3.4e38f;
        }
        if (lane < TOPK) {
            float prob = expf(myv - gmax) / gsum;
            float ww = (prob >= 1e-6f) ? prob : 0.0f;
            int pair = t * TOPK + lane;
            int pe = myi >> 8, rem = myi & 255, me = rem >> 4, oe = rem & 15;
            prei[pair] = pe; mlpi[pair] = me; posti[pair] = oe; w[pair] = ww;
            int s0 = atomicAdd(&cnt[pe], 1);       rows[pe * NPAIR + s0] = pair;
            int s1 = atomicAdd(&cnt[16 + me], 1);  rows[(16 + me) * NPAIR + s1] = pair;
            int s2 = atomicAdd(&cnt[32 + oe], 1);  rows[(32 + oe) * NPAIR + s2] = pair;
        }
    }
}

// ---------------- pre: sum 2 partials + bias + LN + act; also init y=bias ----
__global__ __launch_bounds__(256) void prelnact_k(const float* U, const int* prei,
                                                  const float* pbias,
                                                  const float* g, const float* b, float* X,
                                                  const int* mlpi, const float* mb2, float* y) {
    const int warp = threadIdx.x >> 5, lane = threadIdx.x & 31;
    const int p = blockIdx.x * 8 + warp;
    const int e = prei[p];
    const int e2 = mlpi[p];
    float u[16];
#pragma unroll
    for (int j = 0; j < 16; j++) {
        int idx = lane + 32 * j;
        u[j] = U[p * D + idx] + U[(long)NPAIR * D + p * D + idx] + pbias[e * D + idx];
        y[(long)p * D + idx] = mb2[e2 * D + idx];   // bias-init for mlp2 atomic acc
    }

    float s = 0.0f;
#pragma unroll
    for (int j = 0; j < 16; j++) s += u[j];
    const float mean = wsum(s) * (1.0f / D);

    float v = 0.0f;
#pragma unroll
    for (int j = 0; j < 16; j++) { float d = u[j] - mean; v += d * d; }
    const float rstd = rsqrtf(wsum(v) * (1.0f / D) + 1e-5f);

    const int a = e & 3;
#pragma unroll
    for (int j = 0; j < 16; j++) {
        int idx = lane + 32 * j;
        float val = (u[j] - mean) * rstd * g[e * D + idx] + b[e * D + idx];
        X[p * D + idx] = actf(a, val);
    }
}

// ---------------- post: sum 2 partials + bias + LN + weighted reduce ---------
__global__ __launch_bounds__(256) void final_k(const float* Z, const int* posti, const float* w,
                                               const float* pbias,
                                               const float* g, const float* b, float* out) {
    const int t = blockIdx.x, tid = threadIdx.x;
    const int warp = tid >> 5, lane = tid & 31;
    __shared__ float sacc[8][D];

    const int pair = t * TOPK + warp;
    const int e = posti[pair];
    const float ww = w[pair];
    float z[16];
#pragma unroll
    for (int j = 0; j < 16; j++) {
        int idx = lane + 32 * j;
        z[j] = Z[(long)pair * D + idx] + Z[(long)NPAIR * D + (long)pair * D + idx]
             + pbias[e * D + idx];
    }

    if ((e & 1) == 0) {
        float s = 0.0f;
#pragma unroll
        for (int j = 0; j < 16; j++) s += z[j];
        const float mean = wsum(s) * (1.0f / D);
        float v = 0.0f;
#pragma unroll
        for (int j = 0; j < 16; j++) { float d = z[j] - mean; v += d * d; }
        const float rstd = rsqrtf(wsum(v) * (1.0f / D) + 1e-5f);
#pragma unroll
        for (int j = 0; j < 16; j++) {
            int idx = lane + 32 * j;
            z[j] = (z[j] - mean) * rstd * g[e * D + idx] + b[e * D + idx];
        }
    }
#pragma unroll
    for (int j = 0; j < 16; j++) sacc[warp][lane + 32 * j] = ww * z[j];
    __syncthreads();

    for (int i = tid; i < D; i += 256) {
        float s = 0.0f;
#pragma unroll
        for (int k = 0; k < 8; k++) s += sacc[k][i];
        out[t * D + i] = s;
    }
}

// ---------------- launch -----------------------------------------------------
extern "C" void kernel_launch(void* const* d_in, const int* in_sizes, int n_in,
                              void* d_out, int out_size) {
    const float* x       = (const float*)d_in[0];
    const float* r_w1    = (const float*)d_in[1];
    const float* r_b1    = (const float*)d_in[2];
    const float* r_w2    = (const float*)d_in[3];
    const float* r_b2    = (const float*)d_in[4];
    const float* r_w3    = (const float*)d_in[5];
    const float* r_b3    = (const float*)d_in[6];
    const float* temp    = (const float*)d_in[7];
    const float* pre_w   = (const float*)d_in[8];
    const float* pre_b   = (const float*)d_in[9];
    const float* pre_g   = (const float*)d_in[10];
    const float* pre_be  = (const float*)d_in[11];
    const float* mlp_w1  = (const float*)d_in[12];
    const float* mlp_b1  = (const float*)d_in[13];
    const float* mlp_w2  = (const float*)d_in[14];
    const float* mlp_b2  = (const float*)d_in[15];
    const float* post_w  = (const float*)d_in[16];
    const float* post_b  = (const float*)d_in[17];
    const float* post_g  = (const float*)d_in[18];
    const float* post_be = (const float*)d_in[19];
    float* out = (float*)d_out;

    float *h1, *h2, *sc, *preu, *xin, *hmid, *y, *z, *w;
    int *prei, *mlpi, *posti, *cnt, *rows;
    cudaGetSymbolAddress((void**)&h1, g_h1);
    cudaGetSymbolAddress((void**)&h2, g_h2);
    cudaGetSymbolAddress((void**)&sc, g_scores);
    cudaGetSymbolAddress((void**)&preu, g_preu);
    cudaGetSymbolAddress((void**)&xin, g_xin);
    cudaGetSymbolAddress((void**)&hmid, g_hmid);
    cudaGetSymbolAddress((void**)&y, g_y);
    cudaGetSymbolAddress((void**)&z, g_z);
    cudaGetSymbolAddress((void**)&w, g_w);
    cudaGetSymbolAddress((void**)&prei, g_prei);
    cudaGetSymbolAddress((void**)&mlpi, g_mlpi);
    cudaGetSymbolAddress((void**)&posti, g_posti);
    cudaGetSymbolAddress((void**)&cnt, g_cnt);
    cudaGetSymbolAddress((void**)&rows, g_rows);

    // fc1: split-K=2 (z), partials -> h1[2]; block 0 zeroes routing counters
    {
        GArgs a = {x, D, r_w1, 0, 512, r_b1, 0, h1, 512,
                   T, 512, 256, nullptr, nullptr, 0, 0, 0, 1,
                   (long)T * 512, cnt, 0, nullptr, 0};
        rgemm_k<<<dim3(8, 2, 2), 256>>>(a);
    }
    // fc2: A = gelu(h1p0 + h1p1 + r_b1); split-K=2 -> h2[2]
    {
        GArgs a = {h1, 512, r_w2, 0, 256, r_b2, 0, h2, 256,
                   T, 256, 256, nullptr, nullptr, 0, 0, 0, 1,
                   (long)T * 256, nullptr, 0, r_b1, (long)T * 512};
        rgemm_k<<<dim3(4, 2, 2), 256>>>(a);
    }
    // fc3: A = gelu(h2p0 + h2p1 + r_b2); split-K=2 -> score partials
    {
        GArgs a = {h2, 256, r_w3, 0, NSCORE, r_b3, 0, sc, NSCORE,
                   T, NSCORE, 128, nullptr, nullptr, 0, 0, 0, 0,
                   (long)T * NSCORE, nullptr, 0, r_b2, (long)T * 256};
        rgemm_k<<<dim3(64, 2, 2), 256>>>(a);
    }

    route_k<<<T, 256>>>(sc, r_b3, temp, w, prei, mlpi, posti, cnt, rows);

    // pre: split-K=2, S=4, NW=2 (proven config)
    {
        GArgs a = {x, D, pre_w, (long)D * D, D, pre_b, D, preu, D,
                   NPAIR, D, D, rows, cnt, 3, 0, 0, 0, (long)NPAIR * D,
                   nullptr, 0, nullptr, 0};
        tgemm_k<2, 4, 2><<<dim3(16, 6, NEXP), 64>>>(a);
    }
    // pre LN + act; also initializes y = mlp_b2[mlpi] for mlp2 accumulation
    prelnact_k<<<NPAIR / 8, 256>>>(preu, prei, pre_b, pre_g, pre_be, xin,
                                   mlpi, mlp_b2, y);

    // mlp1: fused bias+act, S=3, NW=4 (4 warps/block -> 28 warps/SM)
    {
        GArgs a = {xin, D, mlp_w1, (long)D * MAXH, MAXH, mlp_b1, MAXH, hmid, MAXH,
                   NPAIR, MAXH, D, rows + 16 * NPAIR, cnt + 16, 0, 1, 0, 5, 0,
                   nullptr, 0, nullptr, 0};
        tgemm_k<1, 3, 4><<<dim3(40, 3, NEXP), 128>>>(a);
    }
    // mlp2: split-K=4, S=3, NW=4, atomic accumulation into bias-initialized y
    {
        GArgs a = {hmid, MAXH, mlp_w2, (long)MAXH * D, D, mlp_b2, D, y, D,
                   NPAIR, D, MAXH, rows + 16 * NPAIR, cnt + 16, 0, 0, 1, 0,
                   0, nullptr, 1, nullptr, 0};
        tgemm_k<4, 3, 4><<<dim3(32, 3, NEXP), 128>>>(a);
    }

    // post: split-K=2, S=4, NW=2
    {
        GArgs a = {y, D, post_w, (long)D * D, D, post_b, D, z, D,
                   NPAIR, D, D, rows + 32 * NPAIR, cnt + 32, 0, 0, 0, 0,
                   (long)NPAIR * D, nullptr, 0, nullptr, 0};
        tgemm_k<2, 4, 2><<<dim3(16, 6, NEXP), 64>>>(a);
    }

    final_k<<<T, 256>>>(z, posti, w, post_b, post_g, post_be, out);
}